// round 11
// baseline (speedup 1.0000x reference)
#include <cuda_runtime.h>
#include <cuda_bf16.h>
#include <math.h>
#include <cstdint>

#define NN 50000
#define NE 800000
#define NPAD 50176
#define INF 128
#define HID 256
#define NCLS 64

// ---------------- device scratch ----------------
__device__ int   g_deg[NN];
__device__ int   g_cursor[NN];
__device__ int   g_off[NN + 1];
__device__ int   g_csr[NE];
__device__ float g_invdeg[NN];
__device__ int   g_tsum[64];
// U stored as 4 contiguous chunks u0,u1,u2,u3; chunk c = g_U + c*NN*64
__device__ __align__(16) float g_U[(size_t)4 * NN * 64];
__device__ __align__(16) float g_s[(size_t)2 * NN * 64];   // s2, s1
// g_pre layout: Us=0, Un=16384, Q0=32768, Q1=49152, Q2=65536
__device__ __align__(16) float g_pre[5 * 256 * 64];
__device__ __align__(16) __nv_bfloat16 g_CTh[256 * 128];   // Cbig^T hi [n][k]
__device__ __align__(16) __nv_bfloat16 g_CTl[256 * 128];   // Cbig^T lo
__device__ __align__(16) __nv_bfloat16 g_xh[(size_t)NPAD * 128];  // x hi
__device__ __align__(16) __nv_bfloat16 g_xl[(size_t)NPAD * 128];  // x lo
__device__ float g_r[3 * 64];
__device__ float g_e1[NN];
__device__ float g_e2[NN];

// ---------------- x -> bf16 hi/lo split (streaming) ----------------
__global__ void k_split(const float* __restrict__ x) {
    int t = blockIdx.x * blockDim.x + threadIdx.x;   // one per 8 elements
    if (t >= NPAD * 16) return;
    uint4 h, l;
    if (t < NN * 16) {
        const float4* xp = (const float4*)x + (size_t)t * 2;
        float4 v0 = xp[0], v1 = xp[1];
        float f[8] = {v0.x, v0.y, v0.z, v0.w, v1.x, v1.y, v1.z, v1.w};
        uint32_t hp[4], lp[4];
        #pragma unroll
        for (int e = 0; e < 4; ++e) {
            __nv_bfloat16 h0 = __float2bfloat16(f[2 * e]);
            __nv_bfloat16 h1 = __float2bfloat16(f[2 * e + 1]);
            float l0 = f[2 * e]     - __bfloat162float(h0);
            float l1 = f[2 * e + 1] - __bfloat162float(h1);
            __nv_bfloat162 hh = __halves2bfloat162(h0, h1);
            __nv_bfloat162 lv = __halves2bfloat162(__float2bfloat16(l0),
                                                   __float2bfloat16(l1));
            hp[e] = *(uint32_t*)&hh;
            lp[e] = *(uint32_t*)&lv;
        }
        h = make_uint4(hp[0], hp[1], hp[2], hp[3]);
        l = make_uint4(lp[0], lp[1], lp[2], lp[3]);
    } else {
        h = make_uint4(0, 0, 0, 0);
        l = make_uint4(0, 0, 0, 0);
    }
    ((uint4*)g_xh)[t] = h;
    ((uint4*)g_xl)[t] = l;
}

// ---------------- CSR build ----------------
__global__ void k_zero_counts() {
    int i = blockIdx.x * blockDim.x + threadIdx.x;
    if (i < NN) { g_deg[i] = 0; g_cursor[i] = 0; }
}

__global__ void k_count(const int* __restrict__ dst) {
    int e = blockIdx.x * blockDim.x + threadIdx.x;
    if (e < NE) atomicAdd(&g_deg[dst[e]], 1);
}

__global__ void k_scan_tiles() {
    __shared__ int sh[1024];
    int t = threadIdx.x;
    int i = blockIdx.x * 1024 + t;
    int v = (i < NN) ? g_deg[i] : 0;
    sh[t] = v;
    __syncthreads();
    for (int d = 1; d < 1024; d <<= 1) {
        int x = 0;
        if (t >= d) x = sh[t - d];
        __syncthreads();
        sh[t] += x;
        __syncthreads();
    }
    if (i < NN) g_off[i] = sh[t] - v;
    if (t == 1023) g_tsum[blockIdx.x] = sh[t];
}

__global__ void k_scan_sums(int ntiles) {
    __shared__ int sh[64];
    int t = threadIdx.x;
    int v = (t < ntiles) ? g_tsum[t] : 0;
    sh[t] = v;
    __syncthreads();
    for (int d = 1; d < 64; d <<= 1) {
        int x = 0;
        if (t >= d) x = sh[t - d];
        __syncthreads();
        sh[t] += x;
        __syncthreads();
    }
    if (t < ntiles) g_tsum[t] = sh[t] - v;
}

__global__ void k_scan_fix() {
    int i = blockIdx.x * blockDim.x + threadIdx.x;
    if (i < NN) {
        g_off[i] += g_tsum[i >> 10];
        int d = g_deg[i];
        g_invdeg[i] = 1.0f / fmaxf((float)d, 1.0f);
        g_e1[i] = (d > 0) ? 1.0f : 0.0f;
    }
    if (i == 0) g_off[NN] = NE;
}

__global__ void k_fill(const int* __restrict__ src, const int* __restrict__ dst) {
    int e = blockIdx.x * blockDim.x + threadIdx.x;
    if (e < NE) {
        int d = dst[e];
        int pos = g_off[d] + atomicAdd(&g_cursor[d], 1);
        g_csr[pos] = src[e];
    }
}

// ---------------- fused precompute stages ----------------
__global__ void k_preA(const float* __restrict__ W2s, const float* __restrict__ W2n,
                       const float* __restrict__ Wfc) {
    int idx = blockIdx.x * blockDim.x + threadIdx.x;
    if (idx >= 2 * 16384) return;
    int which = idx >> 14;
    int j = idx & 16383;
    int r = j >> 6, c = j & 63;
    const float* A = which ? W2n : W2s;
    float acc = 0.f;
    #pragma unroll 8
    for (int k = 0; k < 256; ++k) acc += A[r * 256 + k] * Wfc[k * 64 + c];
    g_pre[which * 16384 + j] = acc;
}

__global__ void k_preB(const float* __restrict__ W1s, const float* __restrict__ W1n) {
    int idx = blockIdx.x * blockDim.x + threadIdx.x;
    if (idx >= 3 * 16384) return;
    int which = idx / 16384;
    int j = idx % 16384;
    int r = j >> 6, c = j & 63;
    const float* Us = g_pre;
    const float* Un = g_pre + 16384;
    float acc = 0.f;
    if (which == 0) {
        #pragma unroll 8
        for (int k = 0; k < 256; ++k) acc += W1s[r * 256 + k] * Us[k * 64 + c];
    } else if (which == 1) {
        #pragma unroll 8
        for (int k = 0; k < 256; ++k)
            acc += W1n[r * 256 + k] * Us[k * 64 + c] + W1s[r * 256 + k] * Un[k * 64 + c];
    } else {
        #pragma unroll 8
        for (int k = 0; k < 256; ++k) acc += W1n[r * 256 + k] * Un[k * 64 + c];
    }
    g_pre[32768 + which * 16384 + j] = acc;
}

__global__ void k_preC(const float* __restrict__ W0s, const float* __restrict__ W0n) {
    int idx = blockIdx.x * blockDim.x + threadIdx.x;
    if (idx >= 4 * 8192) return;
    int chunk = idx >> 13;
    int j = idx & 8191;
    int r = j >> 6, c = j & 63;
    const float* Q0 = g_pre + 32768;
    const float* Q1 = g_pre + 49152;
    const float* Q2 = g_pre + 65536;
    float acc = 0.f;
    if (chunk == 0) {
        #pragma unroll 8
        for (int k = 0; k < 256; ++k) acc += W0s[r * 256 + k] * Q0[k * 64 + c];
    } else if (chunk == 1) {
        #pragma unroll 8
        for (int k = 0; k < 256; ++k)
            acc += W0n[r * 256 + k] * Q0[k * 64 + c] + W0s[r * 256 + k] * Q1[k * 64 + c];
    } else if (chunk == 2) {
        #pragma unroll 8
        for (int k = 0; k < 256; ++k)
            acc += W0n[r * 256 + k] * Q1[k * 64 + c] + W0s[r * 256 + k] * Q2[k * 64 + c];
    } else {
        #pragma unroll 8
        for (int k = 0; k < 256; ++k) acc += W0n[r * 256 + k] * Q2[k * 64 + c];
    }
    __nv_bfloat16 h = __float2bfloat16(acc);
    g_CTh[chunk * 8192 + c * 128 + r] = h;
    g_CTl[chunk * 8192 + c * 128 + r] = __float2bfloat16(acc - __bfloat162float(h));
}

// warp-parallel rvec: one warp per output element (192 outputs)
__global__ void k_rvec(const float* __restrict__ b0, const float* __restrict__ b1,
                       const float* __restrict__ b2, const float* __restrict__ bfc,
                       const float* __restrict__ Wfc) {
    const float* Us = g_pre;
    const float* Un = g_pre + 16384;
    const float* Q0 = g_pre + 32768;
    const float* Q1 = g_pre + 49152;
    const float* Q2 = g_pre + 65536;
    int gw = (blockIdx.x * blockDim.x + threadIdx.x) >> 5;
    int lane = threadIdx.x & 31;
    if (gw >= 192) return;
    int which = gw / 64, c = gw % 64;
    float acc = 0.f;
    if (which == 0) {
        #pragma unroll
        for (int k = lane; k < 256; k += 32)
            acc += b0[k] * Q0[k * 64 + c] + b1[k] * Us[k * 64 + c] + b2[k] * Wfc[k * 64 + c];
    } else if (which == 1) {
        #pragma unroll
        for (int k = lane; k < 256; k += 32)
            acc += b0[k] * Q1[k * 64 + c] + b1[k] * Un[k * 64 + c];
    } else {
        #pragma unroll
        for (int k = lane; k < 256; k += 32)
            acc += b0[k] * Q2[k * 64 + c];
    }
    #pragma unroll
    for (int o = 16; o > 0; o >>= 1)
        acc += __shfl_xor_sync(0xFFFFFFFFu, acc, o);
    if (lane == 0) {
        if (which == 0) acc += bfc[c];
        g_r[gw] = acc;
    }
}

// ---------------- 64-dim mean gather, x8 unrolled, fused add ----------------
// all row strides are 16 float4s. mode: 0 plain ; 1 also g_e2 ; 2 add bias combo
__global__ void k_gather64(const float4* __restrict__ src,
                           const float4* __restrict__ add,
                           float4* __restrict__ out, int mode) {
    int gtid = blockIdx.x * blockDim.x + threadIdx.x;
    int node = gtid >> 4;
    int c = gtid & 15;
    if (node >= NN) return;
    int s = g_off[node], e = g_off[node + 1];
    float4 a0 = make_float4(0.f, 0.f, 0.f, 0.f);
    float4 a1 = make_float4(0.f, 0.f, 0.f, 0.f);
    float4 a2 = make_float4(0.f, 0.f, 0.f, 0.f);
    float4 a3 = make_float4(0.f, 0.f, 0.f, 0.f);
    float ecnt = 0.f;
    int idx = s;
    for (; idx + 8 <= e; idx += 8) {
        int n[8];
        #pragma unroll
        for (int j = 0; j < 8; ++j) n[j] = g_csr[idx + j];
        float4 v[8];
        #pragma unroll
        for (int j = 0; j < 8; ++j) v[j] = src[(size_t)n[j] * 16 + c];
        if (mode == 1 && c == 0) {
            #pragma unroll
            for (int j = 0; j < 8; ++j) ecnt += (g_deg[n[j]] > 0) ? 1.f : 0.f;
        }
        a0.x += v[0].x; a0.y += v[0].y; a0.z += v[0].z; a0.w += v[0].w;
        a1.x += v[1].x; a1.y += v[1].y; a1.z += v[1].z; a1.w += v[1].w;
        a2.x += v[2].x; a2.y += v[2].y; a2.z += v[2].z; a2.w += v[2].w;
        a3.x += v[3].x; a3.y += v[3].y; a3.z += v[3].z; a3.w += v[3].w;
        a0.x += v[4].x; a0.y += v[4].y; a0.z += v[4].z; a0.w += v[4].w;
        a1.x += v[5].x; a1.y += v[5].y; a1.z += v[5].z; a1.w += v[5].w;
        a2.x += v[6].x; a2.y += v[6].y; a2.z += v[6].z; a2.w += v[6].w;
        a3.x += v[7].x; a3.y += v[7].y; a3.z += v[7].z; a3.w += v[7].w;
    }
    for (; idx + 2 <= e; idx += 2) {
        int n0 = g_csr[idx], n1 = g_csr[idx + 1];
        float4 v0 = src[(size_t)n0 * 16 + c];
        float4 v1 = src[(size_t)n1 * 16 + c];
        if (mode == 1 && c == 0)
            ecnt += ((g_deg[n0] > 0) ? 1.f : 0.f) + ((g_deg[n1] > 0) ? 1.f : 0.f);
        a0.x += v0.x; a0.y += v0.y; a0.z += v0.z; a0.w += v0.w;
        a1.x += v1.x; a1.y += v1.y; a1.z += v1.z; a1.w += v1.w;
    }
    if (idx < e) {
        int sn = g_csr[idx];
        float4 v = src[(size_t)sn * 16 + c];
        if (mode == 1 && c == 0) ecnt += (g_deg[sn] > 0) ? 1.f : 0.f;
        a0.x += v.x; a0.y += v.y; a0.z += v.z; a0.w += v.w;
    }
    a0.x += a1.x + a2.x + a3.x;
    a0.y += a1.y + a2.y + a3.y;
    a0.z += a1.z + a2.z + a3.z;
    a0.w += a1.w + a2.w + a3.w;
    float w = g_invdeg[node];
    if (mode == 1 && c == 0) g_e2[node] = ecnt * w;
    float4 r = add[(size_t)node * 16 + c];
    r.x += a0.x * w; r.y += a0.y * w; r.z += a0.z * w; r.w += a0.w * w;
    if (mode == 2) {
        float a = g_e1[node], b = g_e2[node];
        const float4* r0 = (const float4*)g_r;
        const float4* r1 = r0 + 16;
        const float4* r2 = r0 + 32;
        float4 v0 = r0[c], v1 = r1[c], v2 = r2[c];
        r.x += v0.x + a * v1.x + b * v2.x;
        r.y += v0.y + a * v1.y + b * v2.y;
        r.z += v0.z + a * v1.z + b * v2.z;
        r.w += v0.w + a * v1.w + b * v2.w;
    }
    out[(size_t)node * 16 + c] = r;
}

// ---------------- mma.sync bf16 split GEMM, pre-split inputs, 2 CTAs/SM ----------------
// BM=128 x BN=64; grid (4, 391); each block writes one U chunk.
#define LDK 136
#define SM_AH 0
#define SM_AL (128 * LDK)
#define SM_BH (256 * LDK)
#define SM_BL (256 * LDK + 64 * LDK)
#define SM_HALVES (256 * LDK + 128 * LDK)

#define MMA16816(c, a, b0_, b1_) \
    asm volatile("mma.sync.aligned.m16n8k16.row.col.f32.bf16.bf16.f32 " \
        "{%0,%1,%2,%3}, {%4,%5,%6,%7}, {%8,%9}, {%0,%1,%2,%3};" \
        : "+f"((c)[0]), "+f"((c)[1]), "+f"((c)[2]), "+f"((c)[3]) \
        : "r"((a)[0]), "r"((a)[1]), "r"((a)[2]), "r"((a)[3]), \
          "r"(b0_), "r"(b1_))

#define LDSM4(r0, r1, r2, r3, addr) \
    asm volatile("ldmatrix.sync.aligned.m8n8.x4.shared.b16 {%0,%1,%2,%3}, [%4];" \
        : "=r"(r0), "=r"(r1), "=r"(r2), "=r"(r3) : "r"(addr))

__global__ __launch_bounds__(256, 2)
void k_wgemm(const __nv_bfloat16* __restrict__ xh, const __nv_bfloat16* __restrict__ xl,
             const __nv_bfloat16* __restrict__ CTh, const __nv_bfloat16* __restrict__ CTl,
             float* __restrict__ U, int M) {
    extern __shared__ __nv_bfloat16 sm[];
    __nv_bfloat16* Ah = sm + SM_AH;
    __nv_bfloat16* Al = sm + SM_AL;
    __nv_bfloat16* Bh = sm + SM_BH;
    __nv_bfloat16* Bl = sm + SM_BL;

    const int tid = threadIdx.x;
    const int bm = blockIdx.y * 128;
    const int colbase = blockIdx.x * 64;
    const __nv_bfloat16* cth = CTh + (size_t)colbase * 128;
    const __nv_bfloat16* ctl = CTl + (size_t)colbase * 128;

    // ---- stage A: copy 128 pre-split rows (bf16) ----
    {
        int r = tid >> 1;
        int half = tid & 1;
        const uint4* sh = (const uint4*)(xh + (size_t)(bm + r) * 128 + half * 64);
        const uint4* sl = (const uint4*)(xl + (size_t)(bm + r) * 128 + half * 64);
        uint4* dh = (uint4*)(Ah + r * LDK + half * 64);
        uint4* dl = (uint4*)(Al + r * LDK + half * 64);
        #pragma unroll
        for (int j = 0; j < 8; ++j) { dh[j] = sh[j]; dl[j] = sl[j]; }
    }
    // ---- stage B: copy 64 CT rows ----
    if (tid < 128) {
        int r = tid >> 1;
        int half = tid & 1;
        const uint4* sh = (const uint4*)(cth + (size_t)r * 128 + half * 64);
        const uint4* sl = (const uint4*)(ctl + (size_t)r * 128 + half * 64);
        uint4* dh = (uint4*)(Bh + r * LDK + half * 64);
        uint4* dl = (uint4*)(Bl + r * LDK + half * 64);
        #pragma unroll
        for (int j = 0; j < 8; ++j) { dh[j] = sh[j]; dl[j] = sl[j]; }
    }
    __syncthreads();

    const int w = tid >> 5, lane = tid & 31;
    const int wm = (w >> 1) * 32;          // 4 m-groups of 32 rows
    const int wn = (w & 1) * 32;           // 2 n-groups of 32 cols
    const int lr = lane >> 2;
    const int lc = (lane & 3) * 2;
    const int g  = lane >> 3, gl = lane & 7;
    const int a_r = (g & 1) * 8 + gl;      // A: matrices [rows, rows+8] x [k, k+8]
    const int a_c = (g >> 1) * 8;
    const int b_r = (g >> 1) * 8 + gl;     // B: matrices [fn, fn+1] x [k, k+8]
    const int b_c = (g & 1) * 8;

    float acc[2][4][4];
    #pragma unroll
    for (int i = 0; i < 2; ++i)
        #pragma unroll
        for (int j = 0; j < 4; ++j)
            #pragma unroll
            for (int e = 0; e < 4; ++e) acc[i][j][e] = 0.f;

    #pragma unroll
    for (int pass = 0; pass < 3; ++pass) {
        const __nv_bfloat16* As = (pass == 2) ? Al : Ah;
        const __nv_bfloat16* Bs = (pass == 1) ? Bl : Bh;
        #pragma unroll
        for (int ks = 0; ks < 8; ++ks) {
            int kb = ks * 16;
            uint32_t a[2][4];
            #pragma unroll
            for (int fm = 0; fm < 2; ++fm) {
                uint32_t addr = (uint32_t)__cvta_generic_to_shared(
                    &As[(wm + fm * 16 + a_r) * LDK + kb + a_c]);
                LDSM4(a[fm][0], a[fm][1], a[fm][2], a[fm][3], addr);
            }
            uint32_t b[4][2];
            #pragma unroll
            for (int p = 0; p < 2; ++p) {
                uint32_t addr = (uint32_t)__cvta_generic_to_shared(
                    &Bs[(wn + p * 16 + b_r) * LDK + kb + b_c]);
                LDSM4(b[2 * p][0], b[2 * p][1], b[2 * p + 1][0], b[2 * p + 1][1], addr);
            }
            #pragma unroll
            for (int fn = 0; fn < 4; ++fn)
                #pragma unroll
                for (int fm = 0; fm < 2; ++fm)
                    MMA16816(acc[fm][fn], a[fm], b[fn][0], b[fn][1]);
        }
    }

    // ---- epilogue into this block's U chunk ----
    const int chunk = colbase >> 6;
    float* dstbase = U + (size_t)chunk * NN * 64;
    #pragma unroll
    for (int fm = 0; fm < 2; ++fm) {
        int r0 = bm + wm + fm * 16 + lr;
        int r1 = r0 + 8;
        #pragma unroll
        for (int fn = 0; fn < 4; ++fn) {
            int off = (colbase + wn + fn * 8 + lc) & 63;
            if (r0 < M)
                *(float2*)(dstbase + (size_t)r0 * 64 + off) =
                    make_float2(acc[fm][fn][0], acc[fm][fn][1]);
            if (r1 < M)
                *(float2*)(dstbase + (size_t)r1 * 64 + off) =
                    make_float2(acc[fm][fn][2], acc[fm][fn][3]);
        }
    }
}

// ---------------- launch ----------------
extern "C" void kernel_launch(void* const* d_in, const int* in_sizes, int n_in,
                              void* d_out, int out_size) {
    const float* x    = (const float*)d_in[0];
    const int*   esrc = (const int*)d_in[1];
    const int*   edst = (const int*)d_in[2];
    const float* W0s  = (const float*)d_in[3];
    const float* W0n  = (const float*)d_in[4];
    const float* b0   = (const float*)d_in[5];
    const float* W1s  = (const float*)d_in[6];
    const float* W1n  = (const float*)d_in[7];
    const float* b1   = (const float*)d_in[8];
    const float* W2s  = (const float*)d_in[9];
    const float* W2n  = (const float*)d_in[10];
    const float* b2   = (const float*)d_in[11];
    const float* Wfc  = (const float*)d_in[12];
    const float* bfc  = (const float*)d_in[13];
    float* out = (float*)d_out;

    float *U, *sbuf;
    __nv_bfloat16 *CTh, *CTl, *xh, *xl;
    cudaGetSymbolAddress((void**)&U,    g_U);
    cudaGetSymbolAddress((void**)&sbuf, g_s);
    cudaGetSymbolAddress((void**)&CTh,  g_CTh);
    cudaGetSymbolAddress((void**)&CTl,  g_CTl);
    cudaGetSymbolAddress((void**)&xh,   g_xh);
    cudaGetSymbolAddress((void**)&xl,   g_xl);

    const int TB = 256;
    int nblk_n = (NN + TB - 1) / TB;
    int nblk_e = (NE + TB - 1) / TB;
    int ntiles = (NN + 1023) / 1024;

    size_t smem_bytes = (size_t)SM_HALVES * sizeof(__nv_bfloat16);
    cudaFuncSetAttribute(k_wgemm, cudaFuncAttributeMaxDynamicSharedMemorySize,
                         (int)smem_bytes);

    cudaStream_t s2;
    cudaStreamCreateWithFlags(&s2, cudaStreamNonBlocking);
    cudaEvent_t eFork, eSplit, eJoin;
    cudaEventCreateWithFlags(&eFork,  cudaEventDisableTiming);
    cudaEventCreateWithFlags(&eSplit, cudaEventDisableTiming);
    cudaEventCreateWithFlags(&eJoin,  cudaEventDisableTiming);

    cudaEventRecord(eFork, 0);
    cudaStreamWaitEvent(s2, eFork, 0);

    // ---- chain A (stream 0): x split first, then CSR build ----
    k_split<<<(NPAD * 16 + TB - 1) / TB, TB>>>(x);
    cudaEventRecord(eSplit, 0);
    k_zero_counts<<<nblk_n, TB>>>();
    k_count<<<nblk_e, TB>>>(edst);
    k_scan_tiles<<<ntiles, 1024>>>();
    k_scan_sums<<<1, 64>>>(ntiles);
    k_scan_fix<<<nblk_n, TB>>>();
    k_fill<<<nblk_e, TB>>>(esrc, edst);

    // ---- chain B (s2): precompute -> rvec -> GEMM ----
    k_preA<<<(2 * 16384 + TB - 1) / TB, TB, 0, s2>>>(W2s, W2n, Wfc);
    k_preB<<<(3 * 16384 + TB - 1) / TB, TB, 0, s2>>>(W1s, W1n);
    k_preC<<<(4 * 8192 + TB - 1) / TB, TB, 0, s2>>>(W0s, W0n);
    k_rvec<<<24, 256, 0, s2>>>(b0, b1, b2, bfc, Wfc);
    cudaStreamWaitEvent(s2, eSplit, 0);
    {
        dim3 gG(4, (NN + 127) / 128);
        k_wgemm<<<gG, 256, smem_bytes, s2>>>(xh, xl, CTh, CTl, U, NN);
    }
    cudaEventRecord(eJoin, s2);

    // join
    cudaStreamWaitEvent(0, eJoin, 0);

    // ---- Horner aggregation over chunked U ----
    const float4* u0 = (const float4*)U;
    const float4* u1 = (const float4*)(U + (size_t)1 * NN * 64);
    const float4* u2 = (const float4*)(U + (size_t)2 * NN * 64);
    const float4* u3 = (const float4*)(U + (size_t)3 * NN * 64);
    float4* s2buf = (float4*)sbuf;
    float4* s1buf = (float4*)(sbuf + (size_t)NN * 64);
    int gblk = (NN * 16 + TB - 1) / TB;
    k_gather64<<<gblk, TB>>>(u3, u2, s2buf, 1);
    k_gather64<<<gblk, TB>>>(s2buf, u1, s1buf, 0);
    k_gather64<<<gblk, TB>>>(s1buf, u0, (float4*)out, 2);
}

// round 12
// speedup vs baseline: 1.2084x; 1.2084x over previous
#include <cuda_runtime.h>
#include <cuda_bf16.h>
#include <cuda_fp16.h>
#include <math.h>
#include <cstdint>

#define NN 50000
#define NE 800000
#define INF 128
#define HID 256
#define NCLS 64

// ---------------- device scratch ----------------
__device__ int   g_deg[NN];
__device__ int   g_cursor[NN];
__device__ int   g_off[NN + 1];
__device__ int   g_csr[NE];
__device__ float g_invdeg[NN];
__device__ int   g_tsum[64];
// U chunks u0,u1,u2 fp32; chunk3 region reused as fp16 u3
__device__ __align__(16) float g_U[(size_t)4 * NN * 64];
__device__ __align__(16) __half g_sh[(size_t)2 * NN * 64];   // s2h, s1h (fp16)
// g_pre layout: Us=0, Un=16384, Q0=32768, Q1=49152, Q2=65536
__device__ __align__(16) float g_pre[5 * 256 * 64];
__device__ __align__(16) __nv_bfloat16 g_CTh[256 * 128];   // Cbig^T hi [n][k]
__device__ __align__(16) __nv_bfloat16 g_CTl[256 * 128];   // Cbig^T lo
__device__ float g_r[3 * 64];
__device__ float g_e1[NN];
__device__ float g_e2[NN];

// ---------------- CSR build ----------------
__global__ void k_zero_counts() {
    int i = blockIdx.x * blockDim.x + threadIdx.x;
    if (i < NN) { g_deg[i] = 0; g_cursor[i] = 0; }
}

__global__ void k_count(const int* __restrict__ dst) {
    int e = blockIdx.x * blockDim.x + threadIdx.x;
    if (e < NE) atomicAdd(&g_deg[dst[e]], 1);
}

__global__ void k_scan_tiles() {
    __shared__ int sh[1024];
    int t = threadIdx.x;
    int i = blockIdx.x * 1024 + t;
    int v = (i < NN) ? g_deg[i] : 0;
    sh[t] = v;
    __syncthreads();
    for (int d = 1; d < 1024; d <<= 1) {
        int x = 0;
        if (t >= d) x = sh[t - d];
        __syncthreads();
        sh[t] += x;
        __syncthreads();
    }
    if (i < NN) g_off[i] = sh[t] - v;
    if (t == 1023) g_tsum[blockIdx.x] = sh[t];
}

__global__ void k_scan_sums(int ntiles) {
    __shared__ int sh[64];
    int t = threadIdx.x;
    int v = (t < ntiles) ? g_tsum[t] : 0;
    sh[t] = v;
    __syncthreads();
    for (int d = 1; d < 64; d <<= 1) {
        int x = 0;
        if (t >= d) x = sh[t - d];
        __syncthreads();
        sh[t] += x;
        __syncthreads();
    }
    if (t < ntiles) g_tsum[t] = sh[t] - v;
}

__global__ void k_scan_fix() {
    int i = blockIdx.x * blockDim.x + threadIdx.x;
    if (i < NN) {
        g_off[i] += g_tsum[i >> 10];
        int d = g_deg[i];
        g_invdeg[i] = 1.0f / fmaxf((float)d, 1.0f);
        g_e1[i] = (d > 0) ? 1.0f : 0.0f;
    }
    if (i == 0) g_off[NN] = NE;
}

__global__ void k_fill(const int* __restrict__ src, const int* __restrict__ dst) {
    int e = blockIdx.x * blockDim.x + threadIdx.x;
    if (e < NE) {
        int d = dst[e];
        int pos = g_off[d] + atomicAdd(&g_cursor[d], 1);
        g_csr[pos] = src[e];
    }
}

// ---------------- fused precompute stages ----------------
__global__ void k_preA(const float* __restrict__ W2s, const float* __restrict__ W2n,
                       const float* __restrict__ Wfc) {
    int idx = blockIdx.x * blockDim.x + threadIdx.x;
    if (idx >= 2 * 16384) return;
    int which = idx >> 14;
    int j = idx & 16383;
    int r = j >> 6, c = j & 63;
    const float* A = which ? W2n : W2s;
    float acc = 0.f;
    #pragma unroll 8
    for (int k = 0; k < 256; ++k) acc += A[r * 256 + k] * Wfc[k * 64 + c];
    g_pre[which * 16384 + j] = acc;
}

__global__ void k_preB(const float* __restrict__ W1s, const float* __restrict__ W1n) {
    int idx = blockIdx.x * blockDim.x + threadIdx.x;
    if (idx >= 3 * 16384) return;
    int which = idx / 16384;
    int j = idx % 16384;
    int r = j >> 6, c = j & 63;
    const float* Us = g_pre;
    const float* Un = g_pre + 16384;
    float acc = 0.f;
    if (which == 0) {
        #pragma unroll 8
        for (int k = 0; k < 256; ++k) acc += W1s[r * 256 + k] * Us[k * 64 + c];
    } else if (which == 1) {
        #pragma unroll 8
        for (int k = 0; k < 256; ++k)
            acc += W1n[r * 256 + k] * Us[k * 64 + c] + W1s[r * 256 + k] * Un[k * 64 + c];
    } else {
        #pragma unroll 8
        for (int k = 0; k < 256; ++k) acc += W1n[r * 256 + k] * Un[k * 64 + c];
    }
    g_pre[32768 + which * 16384 + j] = acc;
}

__global__ void k_preC(const float* __restrict__ W0s, const float* __restrict__ W0n) {
    int idx = blockIdx.x * blockDim.x + threadIdx.x;
    if (idx >= 4 * 8192) return;
    int chunk = idx >> 13;
    int j = idx & 8191;
    int r = j >> 6, c = j & 63;
    const float* Q0 = g_pre + 32768;
    const float* Q1 = g_pre + 49152;
    const float* Q2 = g_pre + 65536;
    float acc = 0.f;
    if (chunk == 0) {
        #pragma unroll 8
        for (int k = 0; k < 256; ++k) acc += W0s[r * 256 + k] * Q0[k * 64 + c];
    } else if (chunk == 1) {
        #pragma unroll 8
        for (int k = 0; k < 256; ++k)
            acc += W0n[r * 256 + k] * Q0[k * 64 + c] + W0s[r * 256 + k] * Q1[k * 64 + c];
    } else if (chunk == 2) {
        #pragma unroll 8
        for (int k = 0; k < 256; ++k)
            acc += W0n[r * 256 + k] * Q1[k * 64 + c] + W0s[r * 256 + k] * Q2[k * 64 + c];
    } else {
        #pragma unroll 8
        for (int k = 0; k < 256; ++k) acc += W0n[r * 256 + k] * Q2[k * 64 + c];
    }
    __nv_bfloat16 h = __float2bfloat16(acc);
    g_CTh[chunk * 8192 + c * 128 + r] = h;
    g_CTl[chunk * 8192 + c * 128 + r] = __float2bfloat16(acc - __bfloat162float(h));
}

// warp-parallel rvec: one warp per output element (192 outputs)
__global__ void k_rvec(const float* __restrict__ b0, const float* __restrict__ b1,
                       const float* __restrict__ b2, const float* __restrict__ bfc,
                       const float* __restrict__ Wfc) {
    const float* Us = g_pre;
    const float* Un = g_pre + 16384;
    const float* Q0 = g_pre + 32768;
    const float* Q1 = g_pre + 49152;
    const float* Q2 = g_pre + 65536;
    int gw = (blockIdx.x * blockDim.x + threadIdx.x) >> 5;
    int lane = threadIdx.x & 31;
    if (gw >= 192) return;
    int which = gw / 64, c = gw % 64;
    float acc = 0.f;
    if (which == 0) {
        #pragma unroll
        for (int k = lane; k < 256; k += 32)
            acc += b0[k] * Q0[k * 64 + c] + b1[k] * Us[k * 64 + c] + b2[k] * Wfc[k * 64 + c];
    } else if (which == 1) {
        #pragma unroll
        for (int k = lane; k < 256; k += 32)
            acc += b0[k] * Q1[k * 64 + c] + b1[k] * Un[k * 64 + c];
    } else {
        #pragma unroll
        for (int k = lane; k < 256; k += 32)
            acc += b0[k] * Q2[k * 64 + c];
    }
    #pragma unroll
    for (int o = 16; o > 0; o >>= 1)
        acc += __shfl_xor_sync(0xFFFFFFFFu, acc, o);
    if (lane == 0) {
        if (which == 0) acc += bfc[c];
        g_r[gw] = acc;
    }
}

// ---------------- 64-dim mean gather over fp16 src ----------------
// src: fp16 rows (8 uint4/row). add: fp32 rows (16 float4/row).
// out: mode 0/1 -> fp16 rows ; mode 2 -> fp32 rows (+ bias combo).
// 8 threads per node; thread c handles cols [8c, 8c+8).
__global__ void k_gather64h(const uint4* __restrict__ src,
                            const float4* __restrict__ add,
                            void* __restrict__ out, int mode) {
    int gtid = blockIdx.x * blockDim.x + threadIdx.x;
    int node = gtid >> 3;
    int c = gtid & 7;
    if (node >= NN) return;
    int s = g_off[node], e = g_off[node + 1];
    float acc0[8] = {0.f, 0.f, 0.f, 0.f, 0.f, 0.f, 0.f, 0.f};
    float acc1[8] = {0.f, 0.f, 0.f, 0.f, 0.f, 0.f, 0.f, 0.f};
    float ecnt = 0.f;
    int idx = s;
    for (; idx + 8 <= e; idx += 8) {
        int n[8];
        #pragma unroll
        for (int j = 0; j < 8; ++j) n[j] = g_csr[idx + j];
        uint4 v[8];
        #pragma unroll
        for (int j = 0; j < 8; ++j) v[j] = src[(size_t)n[j] * 8 + c];
        if (mode == 1 && c == 0) {
            #pragma unroll
            for (int j = 0; j < 8; ++j) ecnt += (g_deg[n[j]] > 0) ? 1.f : 0.f;
        }
        #pragma unroll
        for (int j = 0; j < 8; ++j) {
            const __half2* h = (const __half2*)&v[j];
            float* A = (j & 1) ? acc1 : acc0;
            float2 f0 = __half22float2(h[0]);
            float2 f1 = __half22float2(h[1]);
            float2 f2 = __half22float2(h[2]);
            float2 f3 = __half22float2(h[3]);
            A[0] += f0.x; A[1] += f0.y; A[2] += f1.x; A[3] += f1.y;
            A[4] += f2.x; A[5] += f2.y; A[6] += f3.x; A[7] += f3.y;
        }
    }
    for (; idx < e; ++idx) {
        int sn = g_csr[idx];
        uint4 v = src[(size_t)sn * 8 + c];
        if (mode == 1 && c == 0) ecnt += (g_deg[sn] > 0) ? 1.f : 0.f;
        const __half2* h = (const __half2*)&v;
        float2 f0 = __half22float2(h[0]);
        float2 f1 = __half22float2(h[1]);
        float2 f2 = __half22float2(h[2]);
        float2 f3 = __half22float2(h[3]);
        acc0[0] += f0.x; acc0[1] += f0.y; acc0[2] += f1.x; acc0[3] += f1.y;
        acc0[4] += f2.x; acc0[5] += f2.y; acc0[6] += f3.x; acc0[7] += f3.y;
    }
    float w = g_invdeg[node];
    if (mode == 1 && c == 0) g_e2[node] = ecnt * w;
    float4 d0 = add[(size_t)node * 16 + 2 * c];
    float4 d1 = add[(size_t)node * 16 + 2 * c + 1];
    float f[8];
    f[0] = d0.x + (acc0[0] + acc1[0]) * w;
    f[1] = d0.y + (acc0[1] + acc1[1]) * w;
    f[2] = d0.z + (acc0[2] + acc1[2]) * w;
    f[3] = d0.w + (acc0[3] + acc1[3]) * w;
    f[4] = d1.x + (acc0[4] + acc1[4]) * w;
    f[5] = d1.y + (acc0[5] + acc1[5]) * w;
    f[6] = d1.z + (acc0[6] + acc1[6]) * w;
    f[7] = d1.w + (acc0[7] + acc1[7]) * w;
    if (mode == 2) {
        float a = g_e1[node], b = g_e2[node];
        #pragma unroll
        for (int i = 0; i < 8; ++i) {
            int col = c * 8 + i;
            f[i] += g_r[col] + a * g_r[64 + col] + b * g_r[128 + col];
        }
        float4* o = (float4*)out;
        o[(size_t)node * 16 + 2 * c]     = make_float4(f[0], f[1], f[2], f[3]);
        o[(size_t)node * 16 + 2 * c + 1] = make_float4(f[4], f[5], f[6], f[7]);
    } else {
        uint4 hv;
        __half2 h0 = __floats2half2_rn(f[0], f[1]);
        __half2 h1 = __floats2half2_rn(f[2], f[3]);
        __half2 h2 = __floats2half2_rn(f[4], f[5]);
        __half2 h3 = __floats2half2_rn(f[6], f[7]);
        hv.x = *(uint32_t*)&h0; hv.y = *(uint32_t*)&h1;
        hv.z = *(uint32_t*)&h2; hv.w = *(uint32_t*)&h3;
        ((uint4*)out)[(size_t)node * 8 + c] = hv;
    }
}

// ---------------- mma.sync bf16 split GEMM (R10 proven), fp16 chunk-3 out ------
#define LDK 136
#define SM_AH 0
#define SM_AL (128 * LDK)
#define SM_BH (2 * 128 * LDK)
#define SM_BL (3 * 128 * LDK)
#define SM_HALVES (4 * 128 * LDK)

#define MMA16816(c, a, b0_, b1_) \
    asm volatile("mma.sync.aligned.m16n8k16.row.col.f32.bf16.bf16.f32 " \
        "{%0,%1,%2,%3}, {%4,%5,%6,%7}, {%8,%9}, {%0,%1,%2,%3};" \
        : "+f"((c)[0]), "+f"((c)[1]), "+f"((c)[2]), "+f"((c)[3]) \
        : "r"((a)[0]), "r"((a)[1]), "r"((a)[2]), "r"((a)[3]), \
          "r"(b0_), "r"(b1_))

#define LDSM4(r0, r1, r2, r3, addr) \
    asm volatile("ldmatrix.sync.aligned.m8n8.x4.shared.b16 {%0,%1,%2,%3}, [%4];" \
        : "=r"(r0), "=r"(r1), "=r"(r2), "=r"(r3) : "r"(addr))

__global__ __launch_bounds__(256, 1)
void k_wgemm(const float* __restrict__ x, const __nv_bfloat16* __restrict__ CTh,
             const __nv_bfloat16* __restrict__ CTl, float* __restrict__ U,
             __half* __restrict__ u3h, int M) {
    extern __shared__ __nv_bfloat16 sm[];
    __nv_bfloat16* Ah = sm + SM_AH;
    __nv_bfloat16* Al = sm + SM_AL;
    __nv_bfloat16* Bh = sm + SM_BH;
    __nv_bfloat16* Bl = sm + SM_BL;

    const int tid = threadIdx.x;
    const int bm = blockIdx.y * 128;
    const int colbase = blockIdx.x * 128;
    const __nv_bfloat16* cth = CTh + (size_t)colbase * 128;
    const __nv_bfloat16* ctl = CTl + (size_t)colbase * 128;

    // ---- stage A: rows bm..bm+127 of x -> bf16 hi/lo ----
    {
        int r = tid >> 1;
        int half = tid & 1;
        int grow = bm + r;
        const float4* xr = (const float4*)(x + (size_t)grow * 128 + half * 64);
        __nv_bfloat16* ah = Ah + r * LDK + half * 64;
        __nv_bfloat16* al = Al + r * LDK + half * 64;
        #pragma unroll
        for (int j = 0; j < 8; ++j) {
            float f[8];
            if (grow < M) {
                float4 v0 = xr[2 * j], v1 = xr[2 * j + 1];
                f[0] = v0.x; f[1] = v0.y; f[2] = v0.z; f[3] = v0.w;
                f[4] = v1.x; f[5] = v1.y; f[6] = v1.z; f[7] = v1.w;
            } else {
                #pragma unroll
                for (int e = 0; e < 8; ++e) f[e] = 0.f;
            }
            uint32_t hp[4], lp[4];
            #pragma unroll
            for (int e = 0; e < 4; ++e) {
                __nv_bfloat16 h0 = __float2bfloat16(f[2 * e]);
                __nv_bfloat16 h1 = __float2bfloat16(f[2 * e + 1]);
                float l0 = f[2 * e]     - __bfloat162float(h0);
                float l1 = f[2 * e + 1] - __bfloat162float(h1);
                __nv_bfloat162 hh = __halves2bfloat162(h0, h1);
                __nv_bfloat162 lv = __halves2bfloat162(__float2bfloat16(l0),
                                                       __float2bfloat16(l1));
                hp[e] = *(uint32_t*)&hh;
                lp[e] = *(uint32_t*)&lv;
            }
            *(uint4*)(ah + 8 * j) = make_uint4(hp[0], hp[1], hp[2], hp[3]);
            *(uint4*)(al + 8 * j) = make_uint4(lp[0], lp[1], lp[2], lp[3]);
        }
    }
    // ---- stage B: 128 CT rows of this column half ----
    {
        int r = tid >> 1;
        int half = tid & 1;
        const uint4* sh = (const uint4*)(cth + (size_t)r * 128 + half * 64);
        const uint4* sl = (const uint4*)(ctl + (size_t)r * 128 + half * 64);
        uint4* dh = (uint4*)(Bh + r * LDK + half * 64);
        uint4* dl = (uint4*)(Bl + r * LDK + half * 64);
        #pragma unroll
        for (int j = 0; j < 8; ++j) { dh[j] = sh[j]; dl[j] = sl[j]; }
    }
    __syncthreads();

    const int w = tid >> 5, lane = tid & 31;
    const int wm = (w >> 2) * 64;
    const int wn = (w & 3) * 32;
    const int lr = lane >> 2;
    const int lc = (lane & 3) * 2;
    const int g  = lane >> 3, gl = lane & 7;
    const int a_r = (g & 1) * 8 + gl;
    const int a_c = (g >> 1) * 8;
    const int b_r = (g >> 1) * 8 + gl;
    const int b_c = (g & 1) * 8;

    float acc[4][4][4];
    #pragma unroll
    for (int i = 0; i < 4; ++i)
        #pragma unroll
        for (int j = 0; j < 4; ++j)
            #pragma unroll
            for (int e = 0; e < 4; ++e) acc[i][j][e] = 0.f;

    #pragma unroll
    for (int pass = 0; pass < 3; ++pass) {
        const __nv_bfloat16* As = (pass == 2) ? Al : Ah;
        const __nv_bfloat16* Bs = (pass == 1) ? Bl : Bh;
        #pragma unroll
        for (int ks = 0; ks < 8; ++ks) {
            int kb = ks * 16;
            uint32_t a[4][4];
            #pragma unroll
            for (int fm = 0; fm < 4; ++fm) {
                uint32_t addr = (uint32_t)__cvta_generic_to_shared(
                    &As[(wm + fm * 16 + a_r) * LDK + kb + a_c]);
                LDSM4(a[fm][0], a[fm][1], a[fm][2], a[fm][3], addr);
            }
            uint32_t b[4][2];
            #pragma unroll
            for (int p = 0; p < 2; ++p) {
                uint32_t addr = (uint32_t)__cvta_generic_to_shared(
                    &Bs[(wn + p * 16 + b_r) * LDK + kb + b_c]);
                LDSM4(b[2 * p][0], b[2 * p][1], b[2 * p + 1][0], b[2 * p + 1][1], addr);
            }
            #pragma unroll
            for (int fn = 0; fn < 4; ++fn)
                #pragma unroll
                for (int fm = 0; fm < 4; ++fm)
                    MMA16816(acc[fm][fn], a[fm], b[fn][0], b[fn][1]);
        }
    }

    // ---- epilogue: chunks 0-2 fp32, chunk 3 fp16 ----
    #pragma unroll
    for (int fm = 0; fm < 4; ++fm) {
        int r0 = bm + wm + fm * 16 + lr;
        int r1 = r0 + 8;
        #pragma unroll
        for (int fn = 0; fn < 4; ++fn) {
            int col = colbase + wn + fn * 8 + lc;
            int chunk = col >> 6, off = col & 63;
            if (chunk == 3) {
                if (r0 < M) {
                    __half2 h = __floats2half2_rn(acc[fm][fn][0], acc[fm][fn][1]);
                    *(__half2*)(u3h + (size_t)r0 * 64 + off) = h;
                }
                if (r1 < M) {
                    __half2 h = __floats2half2_rn(acc[fm][fn][2], acc[fm][fn][3]);
                    *(__half2*)(u3h + (size_t)r1 * 64 + off) = h;
                }
            } else {
                float* dst = U + (size_t)chunk * NN * 64 + off;
                if (r0 < M)
                    *(float2*)(dst + (size_t)r0 * 64) =
                        make_float2(acc[fm][fn][0], acc[fm][fn][1]);
                if (r1 < M)
                    *(float2*)(dst + (size_t)r1 * 64) =
                        make_float2(acc[fm][fn][2], acc[fm][fn][3]);
            }
        }
    }
}

// ---------------- launch ----------------
extern "C" void kernel_launch(void* const* d_in, const int* in_sizes, int n_in,
                              void* d_out, int out_size) {
    const float* x    = (const float*)d_in[0];
    const int*   esrc = (const int*)d_in[1];
    const int*   edst = (const int*)d_in[2];
    const float* W0s  = (const float*)d_in[3];
    const float* W0n  = (const float*)d_in[4];
    const float* b0   = (const float*)d_in[5];
    const float* W1s  = (const float*)d_in[6];
    const float* W1n  = (const float*)d_in[7];
    const float* b1   = (const float*)d_in[8];
    const float* W2s  = (const float*)d_in[9];
    const float* W2n  = (const float*)d_in[10];
    const float* b2   = (const float*)d_in[11];
    const float* Wfc  = (const float*)d_in[12];
    const float* bfc  = (const float*)d_in[13];
    float* out = (float*)d_out;

    float *U;
    __half *sh;
    __nv_bfloat16 *CTh, *CTl;
    cudaGetSymbolAddress((void**)&U,   g_U);
    cudaGetSymbolAddress((void**)&sh,  g_sh);
    cudaGetSymbolAddress((void**)&CTh, g_CTh);
    cudaGetSymbolAddress((void**)&CTl, g_CTl);

    const int TB = 256;
    int nblk_n = (NN + TB - 1) / TB;
    int nblk_e = (NE + TB - 1) / TB;
    int ntiles = (NN + 1023) / 1024;

    size_t smem_bytes = (size_t)SM_HALVES * sizeof(__nv_bfloat16);
    cudaFuncSetAttribute(k_wgemm, cudaFuncAttributeMaxDynamicSharedMemorySize,
                         (int)smem_bytes);

    cudaStream_t s2;
    cudaStreamCreateWithFlags(&s2, cudaStreamNonBlocking);
    cudaEvent_t eFork, eJoin;
    cudaEventCreateWithFlags(&eFork, cudaEventDisableTiming);
    cudaEventCreateWithFlags(&eJoin, cudaEventDisableTiming);

    cudaEventRecord(eFork, 0);
    cudaStreamWaitEvent(s2, eFork, 0);

    __half* u3h = (__half*)(U + (size_t)3 * NN * 64);

    // ---- chain B (s2): precompute -> rvec -> full GEMM ----
    k_preA<<<(2 * 16384 + TB - 1) / TB, TB, 0, s2>>>(W2s, W2n, Wfc);
    k_preB<<<(3 * 16384 + TB - 1) / TB, TB, 0, s2>>>(W1s, W1n);
    k_preC<<<(4 * 8192 + TB - 1) / TB, TB, 0, s2>>>(W0s, W0n);
    k_rvec<<<24, 256, 0, s2>>>(b0, b1, b2, bfc, Wfc);
    {
        dim3 gG(2, (NN + 127) / 128);
        k_wgemm<<<gG, 256, smem_bytes, s2>>>(x, CTh, CTl, U, u3h, NN);
    }
    cudaEventRecord(eJoin, s2);

    // ---- chain A (default stream): CSR build ----
    k_zero_counts<<<nblk_n, TB>>>();
    k_count<<<nblk_e, TB>>>(edst);
    k_scan_tiles<<<ntiles, 1024>>>();
    k_scan_sums<<<1, 64>>>(ntiles);
    k_scan_fix<<<nblk_n, TB>>>();
    k_fill<<<nblk_e, TB>>>(esrc, edst);

    // join
    cudaStreamWaitEvent(0, eJoin, 0);

    // ---- Horner aggregation (fp16 srcs) ----
    const float4* u0 = (const float4*)U;
    const float4* u1 = (const float4*)(U + (size_t)1 * NN * 64);
    const float4* u2 = (const float4*)(U + (size_t)2 * NN * 64);
    __half* s2h = sh;
    __half* s1h = sh + (size_t)NN * 64;
    int gblk = (NN * 8 + TB - 1) / TB;
    k_gather64h<<<gblk, TB>>>((const uint4*)u3h, u2, s2h, 1);
    k_gather64h<<<gblk, TB>>>((const uint4*)s2h, u1, s1h, 0);
    k_gather64h<<<gblk, TB>>>((const uint4*)s1h, u0, out, 2);
}

// round 14
// speedup vs baseline: 1.3039x; 1.0790x over previous
#include <cuda_runtime.h>
#include <cuda_bf16.h>
#include <cuda_fp16.h>
#include <math.h>
#include <cstdint>

#define NN 50000
#define NE 800000
#define INF 128
#define HID 256
#define NCLS 64

// ---------------- device scratch ----------------
__device__ int   g_deg[NN];
__device__ int   g_cursor[NN];
__device__ int   g_off[NN + 1];
__device__ int   g_csr[NE];
__device__ float g_invdeg[NN];
__device__ int   g_tsum[64];
// U chunks u0,u1,u2 fp32; chunk3 region reused as fp16 u3
__device__ __align__(16) float g_U[(size_t)4 * NN * 64];
__device__ __align__(16) __half g_sh[(size_t)2 * NN * 64];   // s2h, s1h (fp16)
// g_pre layout: Us=0, Un=16384, Q0=32768, Q1=49152, Q2=65536
__device__ __align__(16) float g_pre[5 * 256 * 64];
__device__ __align__(16) __nv_bfloat16 g_CTh[256 * 128];   // Cbig^T hi [n][k]
__device__ __align__(16) __nv_bfloat16 g_CTl[256 * 128];   // Cbig^T lo
__device__ float g_r[3 * 64];
__device__ float g_e1[NN];
__device__ float g_e2[NN];

// ---------------- CSR build ----------------
__global__ void k_zero_counts() {
    int i = blockIdx.x * blockDim.x + threadIdx.x;
    if (i < NN) { g_deg[i] = 0; g_cursor[i] = 0; }
}

__global__ void k_count(const int* __restrict__ dst) {
    int e = blockIdx.x * blockDim.x + threadIdx.x;
    if (e < NE) atomicAdd(&g_deg[dst[e]], 1);
}

__global__ void k_scan_tiles() {
    __shared__ int sh[1024];
    int t = threadIdx.x;
    int i = blockIdx.x * 1024 + t;
    int v = (i < NN) ? g_deg[i] : 0;
    sh[t] = v;
    __syncthreads();
    for (int d = 1; d < 1024; d <<= 1) {
        int x = 0;
        if (t >= d) x = sh[t - d];
        __syncthreads();
        sh[t] += x;
        __syncthreads();
    }
    if (i < NN) g_off[i] = sh[t] - v;
    if (t == 1023) g_tsum[blockIdx.x] = sh[t];
}

__global__ void k_scan_sums(int ntiles) {
    __shared__ int sh[64];
    int t = threadIdx.x;
    int v = (t < ntiles) ? g_tsum[t] : 0;
    sh[t] = v;
    __syncthreads();
    for (int d = 1; d < 64; d <<= 1) {
        int x = 0;
        if (t >= d) x = sh[t - d];
        __syncthreads();
        sh[t] += x;
        __syncthreads();
    }
    if (t < ntiles) g_tsum[t] = sh[t] - v;
}

__global__ void k_scan_fix() {
    int i = blockIdx.x * blockDim.x + threadIdx.x;
    if (i < NN) {
        g_off[i] += g_tsum[i >> 10];
        int d = g_deg[i];
        g_invdeg[i] = 1.0f / fmaxf((float)d, 1.0f);
        g_e1[i] = (d > 0) ? 1.0f : 0.0f;
    }
    if (i == 0) g_off[NN] = NE;
}

__global__ void k_fill(const int* __restrict__ src, const int* __restrict__ dst) {
    int e = blockIdx.x * blockDim.x + threadIdx.x;
    if (e < NE) {
        int d = dst[e];
        int pos = g_off[d] + atomicAdd(&g_cursor[d], 1);
        g_csr[pos] = src[e];
    }
}

// ---------------- fused precompute stages ----------------
__global__ void k_preA(const float* __restrict__ W2s, const float* __restrict__ W2n,
                       const float* __restrict__ Wfc) {
    int idx = blockIdx.x * blockDim.x + threadIdx.x;
    if (idx >= 2 * 16384) return;
    int which = idx >> 14;
    int j = idx & 16383;
    int r = j >> 6, c = j & 63;
    const float* A = which ? W2n : W2s;
    float acc = 0.f;
    #pragma unroll 8
    for (int k = 0; k < 256; ++k) acc += A[r * 256 + k] * Wfc[k * 64 + c];
    g_pre[which * 16384 + j] = acc;
}

__global__ void k_preB(const float* __restrict__ W1s, const float* __restrict__ W1n) {
    int idx = blockIdx.x * blockDim.x + threadIdx.x;
    if (idx >= 3 * 16384) return;
    int which = idx / 16384;
    int j = idx % 16384;
    int r = j >> 6, c = j & 63;
    const float* Us = g_pre;
    const float* Un = g_pre + 16384;
    float acc = 0.f;
    if (which == 0) {
        #pragma unroll 8
        for (int k = 0; k < 256; ++k) acc += W1s[r * 256 + k] * Us[k * 64 + c];
    } else if (which == 1) {
        #pragma unroll 8
        for (int k = 0; k < 256; ++k)
            acc += W1n[r * 256 + k] * Us[k * 64 + c] + W1s[r * 256 + k] * Un[k * 64 + c];
    } else {
        #pragma unroll 8
        for (int k = 0; k < 256; ++k) acc += W1n[r * 256 + k] * Un[k * 64 + c];
    }
    g_pre[32768 + which * 16384 + j] = acc;
}

__global__ void k_preC(const float* __restrict__ W0s, const float* __restrict__ W0n) {
    int idx = blockIdx.x * blockDim.x + threadIdx.x;
    if (idx >= 4 * 8192) return;
    int chunk = idx >> 13;
    int j = idx & 8191;
    int r = j >> 6, c = j & 63;
    const float* Q0 = g_pre + 32768;
    const float* Q1 = g_pre + 49152;
    const float* Q2 = g_pre + 65536;
    float acc = 0.f;
    if (chunk == 0) {
        #pragma unroll 8
        for (int k = 0; k < 256; ++k) acc += W0s[r * 256 + k] * Q0[k * 64 + c];
    } else if (chunk == 1) {
        #pragma unroll 8
        for (int k = 0; k < 256; ++k)
            acc += W0n[r * 256 + k] * Q0[k * 64 + c] + W0s[r * 256 + k] * Q1[k * 64 + c];
    } else if (chunk == 2) {
        #pragma unroll 8
        for (int k = 0; k < 256; ++k)
            acc += W0n[r * 256 + k] * Q1[k * 64 + c] + W0s[r * 256 + k] * Q2[k * 64 + c];
    } else {
        #pragma unroll 8
        for (int k = 0; k < 256; ++k) acc += W0n[r * 256 + k] * Q2[k * 64 + c];
    }
    __nv_bfloat16 h = __float2bfloat16(acc);
    g_CTh[chunk * 8192 + c * 128 + r] = h;
    g_CTl[chunk * 8192 + c * 128 + r] = __float2bfloat16(acc - __bfloat162float(h));
}

// warp-parallel rvec: one warp per output element (192 outputs)
__global__ void k_rvec(const float* __restrict__ b0, const float* __restrict__ b1,
                       const float* __restrict__ b2, const float* __restrict__ bfc,
                       const float* __restrict__ Wfc) {
    const float* Us = g_pre;
    const float* Un = g_pre + 16384;
    const float* Q0 = g_pre + 32768;
    const float* Q1 = g_pre + 49152;
    const float* Q2 = g_pre + 65536;
    int gw = (blockIdx.x * blockDim.x + threadIdx.x) >> 5;
    int lane = threadIdx.x & 31;
    if (gw >= 192) return;
    int which = gw / 64, c = gw % 64;
    float acc = 0.f;
    if (which == 0) {
        #pragma unroll
        for (int k = lane; k < 256; k += 32)
            acc += b0[k] * Q0[k * 64 + c] + b1[k] * Us[k * 64 + c] + b2[k] * Wfc[k * 64 + c];
    } else if (which == 1) {
        #pragma unroll
        for (int k = lane; k < 256; k += 32)
            acc += b0[k] * Q1[k * 64 + c] + b1[k] * Un[k * 64 + c];
    } else {
        #pragma unroll
        for (int k = lane; k < 256; k += 32)
            acc += b0[k] * Q2[k * 64 + c];
    }
    #pragma unroll
    for (int o = 16; o > 0; o >>= 1)
        acc += __shfl_xor_sync(0xFFFFFFFFu, acc, o);
    if (lane == 0) {
        if (which == 0) acc += bfc[c];
        g_r[gw] = acc;
    }
}

// ---------------- 64-dim mean gather, fp16 src, fp16-native accumulation ------
// src: fp16 rows (8 uint4/row). add: fp32 rows (16 float4/row).
// out: mode 0/1 -> fp16 rows ; mode 2 -> fp32 rows (+ bias combo).
// 8 threads per node; thread c handles cols [8c, 8c+8).
__global__ void k_gather64h(const uint4* __restrict__ src,
                            const float4* __restrict__ add,
                            void* __restrict__ out, int mode) {
    int gtid = blockIdx.x * blockDim.x + threadIdx.x;
    int node = gtid >> 3;
    int c = gtid & 7;
    if (node >= NN) return;
    int s = g_off[node], e = g_off[node + 1];
    float acc[8] = {0.f, 0.f, 0.f, 0.f, 0.f, 0.f, 0.f, 0.f};
    float ecnt = 0.f;
    int idx = s;
    for (; idx + 8 <= e; idx += 8) {
        int n[8];
        #pragma unroll
        for (int j = 0; j < 8; ++j) n[j] = g_csr[idx + j];
        uint4 v[8];
        #pragma unroll
        for (int j = 0; j < 8; ++j) v[j] = src[(size_t)n[j] * 8 + c];
        if (mode == 1 && c == 0) {
            #pragma unroll
            for (int j = 0; j < 8; ++j) ecnt += (g_deg[n[j]] > 0) ? 1.f : 0.f;
        }
        // fp16-native accumulation over this group of 8, two banks
        __half2 hA[4], hB[4];
        {
            const __half2* h0 = (const __half2*)&v[0];
            const __half2* h1 = (const __half2*)&v[1];
            #pragma unroll
            for (int i = 0; i < 4; ++i) { hA[i] = h0[i]; hB[i] = h1[i]; }
        }
        #pragma unroll
        for (int j = 2; j < 8; j += 2) {
            const __half2* hj0 = (const __half2*)&v[j];
            const __half2* hj1 = (const __half2*)&v[j + 1];
            #pragma unroll
            for (int i = 0; i < 4; ++i) {
                hA[i] = __hadd2(hA[i], hj0[i]);
                hB[i] = __hadd2(hB[i], hj1[i]);
            }
        }
        // flush group sum to fp32
        #pragma unroll
        for (int i = 0; i < 4; ++i) {
            float2 fa = __half22float2(hA[i]);
            float2 fb = __half22float2(hB[i]);
            acc[2 * i]     += fa.x + fb.x;
            acc[2 * i + 1] += fa.y + fb.y;
        }
    }
    for (; idx < e; ++idx) {
        int sn = g_csr[idx];
        uint4 v = src[(size_t)sn * 8 + c];
        if (mode == 1 && c == 0) ecnt += (g_deg[sn] > 0) ? 1.f : 0.f;
        const __half2* h = (const __half2*)&v;
        #pragma unroll
        for (int i = 0; i < 4; ++i) {
            float2 f = __half22float2(h[i]);
            acc[2 * i] += f.x;
            acc[2 * i + 1] += f.y;
        }
    }
    float w = g_invdeg[node];
    if (mode == 1 && c == 0) g_e2[node] = ecnt * w;
    float4 d0 = add[(size_t)node * 16 + 2 * c];
    float4 d1 = add[(size_t)node * 16 + 2 * c + 1];
    float f[8];
    f[0] = d0.x + acc[0] * w;
    f[1] = d0.y + acc[1] * w;
    f[2] = d0.z + acc[2] * w;
    f[3] = d0.w + acc[3] * w;
    f[4] = d1.x + acc[4] * w;
    f[5] = d1.y + acc[5] * w;
    f[6] = d1.z + acc[6] * w;
    f[7] = d1.w + acc[7] * w;
    if (mode == 2) {
        float a = g_e1[node], b = g_e2[node];
        #pragma unroll
        for (int i = 0; i < 8; ++i) {
            int col = c * 8 + i;
            f[i] += g_r[col] + a * g_r[64 + col] + b * g_r[128 + col];
        }
        float4* o = (float4*)out;
        o[(size_t)node * 16 + 2 * c]     = make_float4(f[0], f[1], f[2], f[3]);
        o[(size_t)node * 16 + 2 * c + 1] = make_float4(f[4], f[5], f[6], f[7]);
    } else {
        uint4 hv;
        __half2 h0 = __floats2half2_rn(f[0], f[1]);
        __half2 h1 = __floats2half2_rn(f[2], f[3]);
        __half2 h2 = __floats2half2_rn(f[4], f[5]);
        __half2 h3 = __floats2half2_rn(f[6], f[7]);
        hv.x = *(uint32_t*)&h0; hv.y = *(uint32_t*)&h1;
        hv.z = *(uint32_t*)&h2; hv.w = *(uint32_t*)&h3;
        ((uint4*)out)[(size_t)node * 8 + c] = hv;
    }
}

// ---------------- mma.sync bf16 split GEMM (R10 proven), fp16 chunk-3 out ------
#define LDK 136
#define SM_AH 0
#define SM_AL (128 * LDK)
#define SM_BH (2 * 128 * LDK)
#define SM_BL (3 * 128 * LDK)
#define SM_HALVES (4 * 128 * LDK)

#define MMA16816(c, a, b0_, b1_) \
    asm volatile("mma.sync.aligned.m16n8k16.row.col.f32.bf16.bf16.f32 " \
        "{%0,%1,%2,%3}, {%4,%5,%6,%7}, {%8,%9}, {%0,%1,%2,%3};" \
        : "+f"((c)[0]), "+f"((c)[1]), "+f"((c)[2]), "+f"((c)[3]) \
        : "r"((a)[0]), "r"((a)[1]), "r"((a)[2]), "r"((a)[3]), \
          "r"(b0_), "r"(b1_))

#define LDSM4(r0, r1, r2, r3, addr) \
    asm volatile("ldmatrix.sync.aligned.m8n8.x4.shared.b16 {%0,%1,%2,%3}, [%4];" \
        : "=r"(r0), "=r"(r1), "=r"(r2), "=r"(r3) : "r"(addr))

__global__ __launch_bounds__(256, 1)
void k_wgemm(const float* __restrict__ x, const __nv_bfloat16* __restrict__ CTh,
             const __nv_bfloat16* __restrict__ CTl, float* __restrict__ U,
             __half* __restrict__ u3h, int M) {
    extern __shared__ __nv_bfloat16 sm[];
    __nv_bfloat16* Ah = sm + SM_AH;
    __nv_bfloat16* Al = sm + SM_AL;
    __nv_bfloat16* Bh = sm + SM_BH;
    __nv_bfloat16* Bl = sm + SM_BL;

    const int tid = threadIdx.x;
    const int bm = blockIdx.y * 128;
    const int colbase = blockIdx.x * 128;
    const __nv_bfloat16* cth = CTh + (size_t)colbase * 128;
    const __nv_bfloat16* ctl = CTl + (size_t)colbase * 128;

    {
        int r = tid >> 1;
        int half = tid & 1;
        int grow = bm + r;
        const float4* xr = (const float4*)(x + (size_t)grow * 128 + half * 64);
        __nv_bfloat16* ah = Ah + r * LDK + half * 64;
        __nv_bfloat16* al = Al + r * LDK + half * 64;
        #pragma unroll
        for (int j = 0; j < 8; ++j) {
            float f[8];
            if (grow < M) {
                float4 v0 = xr[2 * j], v1 = xr[2 * j + 1];
                f[0] = v0.x; f[1] = v0.y; f[2] = v0.z; f[3] = v0.w;
                f[4] = v1.x; f[5] = v1.y; f[6] = v1.z; f[7] = v1.w;
            } else {
                #pragma unroll
                for (int e = 0; e < 8; ++e) f[e] = 0.f;
            }
            uint32_t hp[4], lp[4];
            #pragma unroll
            for (int e = 0; e < 4; ++e) {
                __nv_bfloat16 h0 = __float2bfloat16(f[2 * e]);
                __nv_bfloat16 h1 = __float2bfloat16(f[2 * e + 1]);
                float l0 = f[2 * e]     - __bfloat162float(h0);
                float l1 = f[2 * e + 1] - __bfloat162float(h1);
                __nv_bfloat162 hh = __halves2bfloat162(h0, h1);
                __nv_bfloat162 lv = __halves2bfloat162(__float2bfloat16(l0),
                                                       __float2bfloat16(l1));
                hp[e] = *(uint32_t*)&hh;
                lp[e] = *(uint32_t*)&lv;
            }
            *(uint4*)(ah + 8 * j) = make_uint4(hp[0], hp[1], hp[2], hp[3]);
            *(uint4*)(al + 8 * j) = make_uint4(lp[0], lp[1], lp[2], lp[3]);
        }
    }
    {
        int r = tid >> 1;
        int half = tid & 1;
        const uint4* sh = (const uint4*)(cth + (size_t)r * 128 + half * 64);
        const uint4* sl = (const uint4*)(ctl + (size_t)r * 128 + half * 64);
        uint4* dh = (uint4*)(Bh + r * LDK + half * 64);
        uint4* dl = (uint4*)(Bl + r * LDK + half * 64);
        #pragma unroll
        for (int j = 0; j < 8; ++j) { dh[j] = sh[j]; dl[j] = sl[j]; }
    }
    __syncthreads();

    const int w = tid >> 5, lane = tid & 31;
    const int wm = (w >> 2) * 64;
    const int wn = (w & 3) * 32;
    const int lr = lane >> 2;
    const int lc = (lane & 3) * 2;
    const int g  = lane >> 3, gl = lane & 7;
    const int a_r = (g & 1) * 8 + gl;
    const int a_c = (g >> 1) * 8;
    const int b_r = (g >> 1) * 8 + gl;
    const int b_c = (g & 1) * 8;

    float acc[4][4][4];
    #pragma unroll
    for (int i = 0; i < 4; ++i)
        #pragma unroll
        for (int j = 0; j < 4; ++j)
            #pragma unroll
            for (int e = 0; e < 4; ++e) acc[i][j][e] = 0.f;

    #pragma unroll
    for (int pass = 0; pass < 3; ++pass) {
        const __nv_bfloat16* As = (pass == 2) ? Al : Ah;
        const __nv_bfloat16* Bs = (pass == 1) ? Bl : Bh;
        #pragma unroll
        for (int ks = 0; ks < 8; ++ks) {
            int kb = ks * 16;
            uint32_t a[4][4];
            #pragma unroll
            for (int fm = 0; fm < 4; ++fm) {
                uint32_t addr = (uint32_t)__cvta_generic_to_shared(
                    &As[(wm + fm * 16 + a_r) * LDK + kb + a_c]);
                LDSM4(a[fm][0], a[fm][1], a[fm][2], a[fm][3], addr);
            }
            uint32_t b[4][2];
            #pragma unroll
            for (int p = 0; p < 2; ++p) {
                uint32_t addr = (uint32_t)__cvta_generic_to_shared(
                    &Bs[(wn + p * 16 + b_r) * LDK + kb + b_c]);
                LDSM4(b[2 * p][0], b[2 * p][1], b[2 * p + 1][0], b[2 * p + 1][1], addr);
            }
            #pragma unroll
            for (int fn = 0; fn < 4; ++fn)
                #pragma unroll
                for (int fm = 0; fm < 4; ++fm)
                    MMA16816(acc[fm][fn], a[fm], b[fn][0], b[fn][1]);
        }
    }

    #pragma unroll
    for (int fm = 0; fm < 4; ++fm) {
        int r0 = bm + wm + fm * 16 + lr;
        int r1 = r0 + 8;
        #pragma unroll
        for (int fn = 0; fn < 4; ++fn) {
            int col = colbase + wn + fn * 8 + lc;
            int chunk = col >> 6, off = col & 63;
            if (chunk == 3) {
                if (r0 < M) {
                    __half2 h = __floats2half2_rn(acc[fm][fn][0], acc[fm][fn][1]);
                    *(__half2*)(u3h + (size_t)r0 * 64 + off) = h;
                }
                if (r1 < M) {
                    __half2 h = __floats2half2_rn(acc[fm][fn][2], acc[fm][fn][3]);
                    *(__half2*)(u3h + (size_t)r1 * 64 + off) = h;
                }
            } else {
                float* dst = U + (size_t)chunk * NN * 64 + off;
                if (r0 < M)
                    *(float2*)(dst + (size_t)r0 * 64) =
                        make_float2(acc[fm][fn][0], acc[fm][fn][1]);
                if (r1 < M)
                    *(float2*)(dst + (size_t)r1 * 64) =
                        make_float2(acc[fm][fn][2], acc[fm][fn][3]);
            }
        }
    }
}

// ---------------- launch ----------------
extern "C" void kernel_launch(void* const* d_in, const int* in_sizes, int n_in,
                              void* d_out, int out_size) {
    const float* x    = (const float*)d_in[0];
    const int*   esrc = (const int*)d_in[1];
    const int*   edst = (const int*)d_in[2];
    const float* W0s  = (const float*)d_in[3];
    const float* W0n  = (const float*)d_in[4];
    const float* b0   = (const float*)d_in[5];
    const float* W1s  = (const float*)d_in[6];
    const float* W1n  = (const float*)d_in[7];
    const float* b1   = (const float*)d_in[8];
    const float* W2s  = (const float*)d_in[9];
    const float* W2n  = (const float*)d_in[10];
    const float* b2   = (const float*)d_in[11];
    const float* Wfc  = (const float*)d_in[12];
    const float* bfc  = (const float*)d_in[13];
    float* out = (float*)d_out;

    float *U;
    __half *sh;
    __nv_bfloat16 *CTh, *CTl;
    cudaGetSymbolAddress((void**)&U,   g_U);
    cudaGetSymbolAddress((void**)&sh,  g_sh);
    cudaGetSymbolAddress((void**)&CTh, g_CTh);
    cudaGetSymbolAddress((void**)&CTl, g_CTl);

    const int TB = 256;
    int nblk_n = (NN + TB - 1) / TB;
    int nblk_e = (NE + TB - 1) / TB;
    int ntiles = (NN + 1023) / 1024;

    size_t smem_bytes = (size_t)SM_HALVES * sizeof(__nv_bfloat16);
    cudaFuncSetAttribute(k_wgemm, cudaFuncAttributeMaxDynamicSharedMemorySize,
                         (int)smem_bytes);

    // Two-stream pattern (R12-proven: passes the teardown memory check).
    cudaStream_t s2;
    cudaStreamCreateWithFlags(&s2, cudaStreamNonBlocking);
    cudaEvent_t eFork, eJoin;
    cudaEventCreateWithFlags(&eFork, cudaEventDisableTiming);
    cudaEventCreateWithFlags(&eJoin, cudaEventDisableTiming);

    cudaEventRecord(eFork, 0);
    cudaStreamWaitEvent(s2, eFork, 0);

    __half* u3h = (__half*)(U + (size_t)3 * NN * 64);

    // ---- chain B (s2): precompute -> rvec -> full GEMM ----
    k_preA<<<(2 * 16384 + TB - 1) / TB, TB, 0, s2>>>(W2s, W2n, Wfc);
    k_preB<<<(3 * 16384 + TB - 1) / TB, TB, 0, s2>>>(W1s, W1n);
    k_preC<<<(4 * 8192 + TB - 1) / TB, TB, 0, s2>>>(W0s, W0n);
    k_rvec<<<24, 256, 0, s2>>>(b0, b1, b2, bfc, Wfc);
    {
        dim3 gG(2, (NN + 127) / 128);
        k_wgemm<<<gG, 256, smem_bytes, s2>>>(x, CTh, CTl, U, u3h, NN);
    }
    cudaEventRecord(eJoin, s2);

    // ---- chain A (default stream): CSR build ----
    k_zero_counts<<<nblk_n, TB>>>();
    k_count<<<nblk_e, TB>>>(edst);
    k_scan_tiles<<<ntiles, 1024>>>();
    k_scan_sums<<<1, 64>>>(ntiles);
    k_scan_fix<<<nblk_n, TB>>>();
    k_fill<<<nblk_e, TB>>>(esrc, edst);

    // join
    cudaStreamWaitEvent(0, eJoin, 0);

    // ---- Horner aggregation (fp16 srcs, fp16-native accumulation) ----
    const float4* u0 = (const float4*)U;
    const float4* u1 = (const float4*)(U + (size_t)1 * NN * 64);
    const float4* u2 = (const float4*)(U + (size_t)2 * NN * 64);
    __half* s2h = sh;
    __half* s1h = sh + (size_t)NN * 64;
    int gblk = (NN * 8 + TB - 1) / TB;
    k_gather64h<<<gblk, TB>>>((const uint4*)u3h, u2, s2h, 1);
    k_gather64h<<<gblk, TB>>>((const uint4*)s2h, u1, s1h, 0);
    k_gather64h<<<gblk, TB>>>((const uint4*)s1h, u0, out, 2);
}

// round 15
// speedup vs baseline: 1.3389x; 1.0269x over previous
#include <cuda_runtime.h>
#include <cuda_bf16.h>
#include <cuda_fp16.h>
#include <math.h>
#include <cstdint>

#define NN 50000
#define NE 800000
#define INF 128
#define HID 256
#define NCLS 64

// ---------------- device scratch ----------------
__device__ int   g_deg[NN];
__device__ int   g_cursor[NN];
__device__ int   g_off[NN + 1];
__device__ int   g_csr[NE];
__device__ float g_invdeg[NN];
__device__ int   g_tsum[64];
// U chunks u0,u1,u2 fp32; chunk3 region reused as fp16 u3
__device__ __align__(16) float g_U[(size_t)4 * NN * 64];
__device__ __align__(16) __half g_sh[(size_t)2 * NN * 64];   // s2h, s1h (fp16)
// g_pre layout: Us=0, Un=16384, Q0=32768, Q1=49152, Q2=65536
__device__ __align__(16) float g_pre[5 * 256 * 64];
__device__ __align__(16) __nv_bfloat16 g_CTh[256 * 128];   // Cbig^T hi [n][k]
__device__ __align__(16) __nv_bfloat16 g_CTl[256 * 128];   // Cbig^T lo
__device__ float g_r[3 * 64];
__device__ float g_e1[NN];
__device__ float g_e2[NN];

// ---------------- CSR build ----------------
__global__ void k_zero_counts() {
    int i = blockIdx.x * blockDim.x + threadIdx.x;
    if (i < NN) { g_deg[i] = 0; g_cursor[i] = 0; }
}

__global__ void k_count(const int* __restrict__ dst) {
    int e = blockIdx.x * blockDim.x + threadIdx.x;
    if (e < NE) atomicAdd(&g_deg[dst[e]], 1);
}

__global__ void k_scan_tiles() {
    __shared__ int sh[1024];
    int t = threadIdx.x;
    int i = blockIdx.x * 1024 + t;
    int v = (i < NN) ? g_deg[i] : 0;
    sh[t] = v;
    __syncthreads();
    for (int d = 1; d < 1024; d <<= 1) {
        int x = 0;
        if (t >= d) x = sh[t - d];
        __syncthreads();
        sh[t] += x;
        __syncthreads();
    }
    if (i < NN) g_off[i] = sh[t] - v;
    if (t == 1023) g_tsum[blockIdx.x] = sh[t];
}

__global__ void k_scan_sums(int ntiles) {
    __shared__ int sh[64];
    int t = threadIdx.x;
    int v = (t < ntiles) ? g_tsum[t] : 0;
    sh[t] = v;
    __syncthreads();
    for (int d = 1; d < 64; d <<= 1) {
        int x = 0;
        if (t >= d) x = sh[t - d];
        __syncthreads();
        sh[t] += x;
        __syncthreads();
    }
    if (t < ntiles) g_tsum[t] = sh[t] - v;
}

__global__ void k_scan_fix() {
    int i = blockIdx.x * blockDim.x + threadIdx.x;
    if (i < NN) {
        g_off[i] += g_tsum[i >> 10];
        int d = g_deg[i];
        g_invdeg[i] = 1.0f / fmaxf((float)d, 1.0f);
        g_e1[i] = (d > 0) ? 1.0f : 0.0f;
    }
    if (i == 0) g_off[NN] = NE;
}

__global__ void k_fill(const int* __restrict__ src, const int* __restrict__ dst) {
    int e = blockIdx.x * blockDim.x + threadIdx.x;
    if (e < NE) {
        int d = dst[e];
        int pos = g_off[d] + atomicAdd(&g_cursor[d], 1);
        g_csr[pos] = src[e];
    }
}

// ---------------- fused precompute stages ----------------
__global__ void k_preA(const float* __restrict__ W2s, const float* __restrict__ W2n,
                       const float* __restrict__ Wfc) {
    int idx = blockIdx.x * blockDim.x + threadIdx.x;
    if (idx >= 2 * 16384) return;
    int which = idx >> 14;
    int j = idx & 16383;
    int r = j >> 6, c = j & 63;
    const float* A = which ? W2n : W2s;
    float acc = 0.f;
    #pragma unroll 8
    for (int k = 0; k < 256; ++k) acc += A[r * 256 + k] * Wfc[k * 64 + c];
    g_pre[which * 16384 + j] = acc;
}

__global__ void k_preB(const float* __restrict__ W1s, const float* __restrict__ W1n) {
    int idx = blockIdx.x * blockDim.x + threadIdx.x;
    if (idx >= 3 * 16384) return;
    int which = idx / 16384;
    int j = idx % 16384;
    int r = j >> 6, c = j & 63;
    const float* Us = g_pre;
    const float* Un = g_pre + 16384;
    float acc = 0.f;
    if (which == 0) {
        #pragma unroll 8
        for (int k = 0; k < 256; ++k) acc += W1s[r * 256 + k] * Us[k * 64 + c];
    } else if (which == 1) {
        #pragma unroll 8
        for (int k = 0; k < 256; ++k)
            acc += W1n[r * 256 + k] * Us[k * 64 + c] + W1s[r * 256 + k] * Un[k * 64 + c];
    } else {
        #pragma unroll 8
        for (int k = 0; k < 256; ++k) acc += W1n[r * 256 + k] * Un[k * 64 + c];
    }
    g_pre[32768 + which * 16384 + j] = acc;
}

__global__ void k_preC(const float* __restrict__ W0s, const float* __restrict__ W0n) {
    int idx = blockIdx.x * blockDim.x + threadIdx.x;
    if (idx >= 4 * 8192) return;
    int chunk = idx >> 13;
    int j = idx & 8191;
    int r = j >> 6, c = j & 63;
    const float* Q0 = g_pre + 32768;
    const float* Q1 = g_pre + 49152;
    const float* Q2 = g_pre + 65536;
    float acc = 0.f;
    if (chunk == 0) {
        #pragma unroll 8
        for (int k = 0; k < 256; ++k) acc += W0s[r * 256 + k] * Q0[k * 64 + c];
    } else if (chunk == 1) {
        #pragma unroll 8
        for (int k = 0; k < 256; ++k)
            acc += W0n[r * 256 + k] * Q0[k * 64 + c] + W0s[r * 256 + k] * Q1[k * 64 + c];
    } else if (chunk == 2) {
        #pragma unroll 8
        for (int k = 0; k < 256; ++k)
            acc += W0n[r * 256 + k] * Q1[k * 64 + c] + W0s[r * 256 + k] * Q2[k * 64 + c];
    } else {
        #pragma unroll 8
        for (int k = 0; k < 256; ++k) acc += W0n[r * 256 + k] * Q2[k * 64 + c];
    }
    __nv_bfloat16 h = __float2bfloat16(acc);
    g_CTh[chunk * 8192 + c * 128 + r] = h;
    g_CTl[chunk * 8192 + c * 128 + r] = __float2bfloat16(acc - __bfloat162float(h));
}

// warp-parallel rvec: one warp per output element (192 outputs)
__global__ void k_rvec(const float* __restrict__ b0, const float* __restrict__ b1,
                       const float* __restrict__ b2, const float* __restrict__ bfc,
                       const float* __restrict__ Wfc) {
    const float* Us = g_pre;
    const float* Un = g_pre + 16384;
    const float* Q0 = g_pre + 32768;
    const float* Q1 = g_pre + 49152;
    const float* Q2 = g_pre + 65536;
    int gw = (blockIdx.x * blockDim.x + threadIdx.x) >> 5;
    int lane = threadIdx.x & 31;
    if (gw >= 192) return;
    int which = gw / 64, c = gw % 64;
    float acc = 0.f;
    if (which == 0) {
        #pragma unroll
        for (int k = lane; k < 256; k += 32)
            acc += b0[k] * Q0[k * 64 + c] + b1[k] * Us[k * 64 + c] + b2[k] * Wfc[k * 64 + c];
    } else if (which == 1) {
        #pragma unroll
        for (int k = lane; k < 256; k += 32)
            acc += b0[k] * Q1[k * 64 + c] + b1[k] * Un[k * 64 + c];
    } else {
        #pragma unroll
        for (int k = lane; k < 256; k += 32)
            acc += b0[k] * Q2[k * 64 + c];
    }
    #pragma unroll
    for (int o = 16; o > 0; o >>= 1)
        acc += __shfl_xor_sync(0xFFFFFFFFu, acc, o);
    if (lane == 0) {
        if (which == 0) acc += bfc[c];
        g_r[gw] = acc;
    }
}

// ---------------- 64-dim mean gather, fp16 src, fp16-native accumulation ------
__global__ void k_gather64h(const uint4* __restrict__ src,
                            const float4* __restrict__ add,
                            void* __restrict__ out, int mode) {
    int gtid = blockIdx.x * blockDim.x + threadIdx.x;
    int node = gtid >> 3;
    int c = gtid & 7;
    if (node >= NN) return;
    int s = g_off[node], e = g_off[node + 1];
    float acc[8] = {0.f, 0.f, 0.f, 0.f, 0.f, 0.f, 0.f, 0.f};
    float ecnt = 0.f;
    int idx = s;
    for (; idx + 8 <= e; idx += 8) {
        int n[8];
        #pragma unroll
        for (int j = 0; j < 8; ++j) n[j] = g_csr[idx + j];
        uint4 v[8];
        #pragma unroll
        for (int j = 0; j < 8; ++j) v[j] = src[(size_t)n[j] * 8 + c];
        if (mode == 1 && c == 0) {
            #pragma unroll
            for (int j = 0; j < 8; ++j) ecnt += (g_deg[n[j]] > 0) ? 1.f : 0.f;
        }
        __half2 hA[4], hB[4];
        {
            const __half2* h0 = (const __half2*)&v[0];
            const __half2* h1 = (const __half2*)&v[1];
            #pragma unroll
            for (int i = 0; i < 4; ++i) { hA[i] = h0[i]; hB[i] = h1[i]; }
        }
        #pragma unroll
        for (int j = 2; j < 8; j += 2) {
            const __half2* hj0 = (const __half2*)&v[j];
            const __half2* hj1 = (const __half2*)&v[j + 1];
            #pragma unroll
            for (int i = 0; i < 4; ++i) {
                hA[i] = __hadd2(hA[i], hj0[i]);
                hB[i] = __hadd2(hB[i], hj1[i]);
            }
        }
        #pragma unroll
        for (int i = 0; i < 4; ++i) {
            float2 fa = __half22float2(hA[i]);
            float2 fb = __half22float2(hB[i]);
            acc[2 * i]     += fa.x + fb.x;
            acc[2 * i + 1] += fa.y + fb.y;
        }
    }
    for (; idx < e; ++idx) {
        int sn = g_csr[idx];
        uint4 v = src[(size_t)sn * 8 + c];
        if (mode == 1 && c == 0) ecnt += (g_deg[sn] > 0) ? 1.f : 0.f;
        const __half2* h = (const __half2*)&v;
        #pragma unroll
        for (int i = 0; i < 4; ++i) {
            float2 f = __half22float2(h[i]);
            acc[2 * i] += f.x;
            acc[2 * i + 1] += f.y;
        }
    }
    float w = g_invdeg[node];
    if (mode == 1 && c == 0) g_e2[node] = ecnt * w;
    float4 d0 = add[(size_t)node * 16 + 2 * c];
    float4 d1 = add[(size_t)node * 16 + 2 * c + 1];
    float f[8];
    f[0] = d0.x + acc[0] * w;
    f[1] = d0.y + acc[1] * w;
    f[2] = d0.z + acc[2] * w;
    f[3] = d0.w + acc[3] * w;
    f[4] = d1.x + acc[4] * w;
    f[5] = d1.y + acc[5] * w;
    f[6] = d1.z + acc[6] * w;
    f[7] = d1.w + acc[7] * w;
    if (mode == 2) {
        float a = g_e1[node], b = g_e2[node];
        #pragma unroll
        for (int i = 0; i < 8; ++i) {
            int col = c * 8 + i;
            f[i] += g_r[col] + a * g_r[64 + col] + b * g_r[128 + col];
        }
        float4* o = (float4*)out;
        o[(size_t)node * 16 + 2 * c]     = make_float4(f[0], f[1], f[2], f[3]);
        o[(size_t)node * 16 + 2 * c + 1] = make_float4(f[4], f[5], f[6], f[7]);
    } else {
        uint4 hv;
        __half2 h0 = __floats2half2_rn(f[0], f[1]);
        __half2 h1 = __floats2half2_rn(f[2], f[3]);
        __half2 h2 = __floats2half2_rn(f[4], f[5]);
        __half2 h3 = __floats2half2_rn(f[6], f[7]);
        hv.x = *(uint32_t*)&h0; hv.y = *(uint32_t*)&h1;
        hv.z = *(uint32_t*)&h2; hv.w = *(uint32_t*)&h3;
        ((uint4*)out)[(size_t)node * 8 + c] = hv;
    }
}

// ---------------- mma.sync bf16 split GEMM, cp.async B staging + batched A ----
#define LDK 136
#define SM_AH 0
#define SM_AL (128 * LDK)
#define SM_BH (2 * 128 * LDK)
#define SM_BL (3 * 128 * LDK)
#define SM_HALVES (4 * 128 * LDK)

#define MMA16816(c, a, b0_, b1_) \
    asm volatile("mma.sync.aligned.m16n8k16.row.col.f32.bf16.bf16.f32 " \
        "{%0,%1,%2,%3}, {%4,%5,%6,%7}, {%8,%9}, {%0,%1,%2,%3};" \
        : "+f"((c)[0]), "+f"((c)[1]), "+f"((c)[2]), "+f"((c)[3]) \
        : "r"((a)[0]), "r"((a)[1]), "r"((a)[2]), "r"((a)[3]), \
          "r"(b0_), "r"(b1_))

#define LDSM4(r0, r1, r2, r3, addr) \
    asm volatile("ldmatrix.sync.aligned.m8n8.x4.shared.b16 {%0,%1,%2,%3}, [%4];" \
        : "=r"(r0), "=r"(r1), "=r"(r2), "=r"(r3) : "r"(addr))

#define CPASYNC16(dst, src) \
    asm volatile("cp.async.ca.shared.global [%0], [%1], 16;" \
        :: "r"(dst), "l"(src) : "memory")

__global__ __launch_bounds__(256, 1)
void k_wgemm(const float* __restrict__ x, const __nv_bfloat16* __restrict__ CTh,
             const __nv_bfloat16* __restrict__ CTl, float* __restrict__ U,
             __half* __restrict__ u3h, int M) {
    extern __shared__ __nv_bfloat16 sm[];
    __nv_bfloat16* Ah = sm + SM_AH;
    __nv_bfloat16* Al = sm + SM_AL;
    __nv_bfloat16* Bh = sm + SM_BH;
    __nv_bfloat16* Bl = sm + SM_BL;

    const int tid = threadIdx.x;
    const int bm = blockIdx.y * 128;
    const int colbase = blockIdx.x * 128;
    const __nv_bfloat16* cth = CTh + (size_t)colbase * 128;
    const __nv_bfloat16* ctl = CTl + (size_t)colbase * 128;

    const int r = tid >> 1;
    const int half = tid & 1;

    // ---- stage B via cp.async (fire-and-forget, overlaps A conversion) ----
    {
        const char* sh = (const char*)(cth + (size_t)r * 128 + half * 64);
        const char* sl = (const char*)(ctl + (size_t)r * 128 + half * 64);
        uint32_t dh = (uint32_t)__cvta_generic_to_shared(Bh + r * LDK + half * 64);
        uint32_t dl = (uint32_t)__cvta_generic_to_shared(Bl + r * LDK + half * 64);
        #pragma unroll
        for (int j = 0; j < 8; ++j) {
            CPASYNC16(dh + 16 * j, sh + 16 * j);
            CPASYNC16(dl + 16 * j, sl + 16 * j);
        }
        asm volatile("cp.async.commit_group;" ::: "memory");
    }

    // ---- stage A: batch all 16 global loads (MLP=16), then convert+store ----
    {
        int grow = bm + r;
        const float4* xr = (const float4*)(x + (size_t)grow * 128 + half * 64);
        float4 v[16];
        if (grow < M) {
            #pragma unroll
            for (int j = 0; j < 16; ++j) v[j] = xr[j];
        } else {
            #pragma unroll
            for (int j = 0; j < 16; ++j) v[j] = make_float4(0.f, 0.f, 0.f, 0.f);
        }
        __nv_bfloat16* ah = Ah + r * LDK + half * 64;
        __nv_bfloat16* al = Al + r * LDK + half * 64;
        #pragma unroll
        for (int j = 0; j < 8; ++j) {
            float f[8];
            float4 v0 = v[2 * j], v1 = v[2 * j + 1];
            f[0] = v0.x; f[1] = v0.y; f[2] = v0.z; f[3] = v0.w;
            f[4] = v1.x; f[5] = v1.y; f[6] = v1.z; f[7] = v1.w;
            uint32_t hp[4], lp[4];
            #pragma unroll
            for (int e = 0; e < 4; ++e) {
                __nv_bfloat16 h0 = __float2bfloat16(f[2 * e]);
                __nv_bfloat16 h1 = __float2bfloat16(f[2 * e + 1]);
                float l0 = f[2 * e]     - __bfloat162float(h0);
                float l1 = f[2 * e + 1] - __bfloat162float(h1);
                __nv_bfloat162 hh = __halves2bfloat162(h0, h1);
                __nv_bfloat162 lv = __halves2bfloat162(__float2bfloat16(l0),
                                                       __float2bfloat16(l1));
                hp[e] = *(uint32_t*)&hh;
                lp[e] = *(uint32_t*)&lv;
            }
            *(uint4*)(ah + 8 * j) = make_uint4(hp[0], hp[1], hp[2], hp[3]);
            *(uint4*)(al + 8 * j) = make_uint4(lp[0], lp[1], lp[2], lp[3]);
        }
    }
    asm volatile("cp.async.wait_group 0;" ::: "memory");
    __syncthreads();

    const int w = tid >> 5, lane = tid & 31;
    const int wm = (w >> 2) * 64;
    const int wn = (w & 3) * 32;
    const int lr = lane >> 2;
    const int lc = (lane & 3) * 2;
    const int g  = lane >> 3, gl = lane & 7;
    const int a_r = (g & 1) * 8 + gl;
    const int a_c = (g >> 1) * 8;
    const int b_r = (g >> 1) * 8 + gl;
    const int b_c = (g & 1) * 8;

    float acc[4][4][4];
    #pragma unroll
    for (int i = 0; i < 4; ++i)
        #pragma unroll
        for (int j = 0; j < 4; ++j)
            #pragma unroll
            for (int e = 0; e < 4; ++e) acc[i][j][e] = 0.f;

    #pragma unroll
    for (int pass = 0; pass < 3; ++pass) {
        const __nv_bfloat16* As = (pass == 2) ? Al : Ah;
        const __nv_bfloat16* Bs = (pass == 1) ? Bl : Bh;
        #pragma unroll
        for (int ks = 0; ks < 8; ++ks) {
            int kb = ks * 16;
            uint32_t a[4][4];
            #pragma unroll
            for (int fm = 0; fm < 4; ++fm) {
                uint32_t addr = (uint32_t)__cvta_generic_to_shared(
                    &As[(wm + fm * 16 + a_r) * LDK + kb + a_c]);
                LDSM4(a[fm][0], a[fm][1], a[fm][2], a[fm][3], addr);
            }
            uint32_t b[4][2];
            #pragma unroll
            for (int p = 0; p < 2; ++p) {
                uint32_t addr = (uint32_t)__cvta_generic_to_shared(
                    &Bs[(wn + p * 16 + b_r) * LDK + kb + b_c]);
                LDSM4(b[2 * p][0], b[2 * p][1], b[2 * p + 1][0], b[2 * p + 1][1], addr);
            }
            #pragma unroll
            for (int fn = 0; fn < 4; ++fn)
                #pragma unroll
                for (int fm = 0; fm < 4; ++fm)
                    MMA16816(acc[fm][fn], a[fm], b[fn][0], b[fn][1]);
        }
    }

    #pragma unroll
    for (int fm = 0; fm < 4; ++fm) {
        int r0 = bm + wm + fm * 16 + lr;
        int r1 = r0 + 8;
        #pragma unroll
        for (int fn = 0; fn < 4; ++fn) {
            int col = colbase + wn + fn * 8 + lc;
            int chunk = col >> 6, off = col & 63;
            if (chunk == 3) {
                if (r0 < M) {
                    __half2 h = __floats2half2_rn(acc[fm][fn][0], acc[fm][fn][1]);
                    *(__half2*)(u3h + (size_t)r0 * 64 + off) = h;
                }
                if (r1 < M) {
                    __half2 h = __floats2half2_rn(acc[fm][fn][2], acc[fm][fn][3]);
                    *(__half2*)(u3h + (size_t)r1 * 64 + off) = h;
                }
            } else {
                float* dst = U + (size_t)chunk * NN * 64 + off;
                if (r0 < M)
                    *(float2*)(dst + (size_t)r0 * 64) =
                        make_float2(acc[fm][fn][0], acc[fm][fn][1]);
                if (r1 < M)
                    *(float2*)(dst + (size_t)r1 * 64) =
                        make_float2(acc[fm][fn][2], acc[fm][fn][3]);
            }
        }
    }
}

// ---------------- launch ----------------
extern "C" void kernel_launch(void* const* d_in, const int* in_sizes, int n_in,
                              void* d_out, int out_size) {
    const float* x    = (const float*)d_in[0];
    const int*   esrc = (const int*)d_in[1];
    const int*   edst = (const int*)d_in[2];
    const float* W0s  = (const float*)d_in[3];
    const float* W0n  = (const float*)d_in[4];
    const float* b0   = (const float*)d_in[5];
    const float* W1s  = (const float*)d_in[6];
    const float* W1n  = (const float*)d_in[7];
    const float* b1   = (const float*)d_in[8];
    const float* W2s  = (const float*)d_in[9];
    const float* W2n  = (const float*)d_in[10];
    const float* b2   = (const float*)d_in[11];
    const float* Wfc  = (const float*)d_in[12];
    const float* bfc  = (const float*)d_in[13];
    float* out = (float*)d_out;

    float *U;
    __half *sh;
    __nv_bfloat16 *CTh, *CTl;
    cudaGetSymbolAddress((void**)&U,   g_U);
    cudaGetSymbolAddress((void**)&sh,  g_sh);
    cudaGetSymbolAddress((void**)&CTh, g_CTh);
    cudaGetSymbolAddress((void**)&CTl, g_CTl);

    const int TB = 256;
    int nblk_n = (NN + TB - 1) / TB;
    int nblk_e = (NE + TB - 1) / TB;
    int ntiles = (NN + 1023) / 1024;

    size_t smem_bytes = (size_t)SM_HALVES * sizeof(__nv_bfloat16);
    cudaFuncSetAttribute(k_wgemm, cudaFuncAttributeMaxDynamicSharedMemorySize,
                         (int)smem_bytes);

    // Two-stream pattern (teardown-check safe); 3 events as in R9.
    cudaStream_t s2;
    cudaStreamCreateWithFlags(&s2, cudaStreamNonBlocking);
    cudaEvent_t eFork, ePre, eJoin;
    cudaEventCreateWithFlags(&eFork, cudaEventDisableTiming);
    cudaEventCreateWithFlags(&ePre,  cudaEventDisableTiming);
    cudaEventCreateWithFlags(&eJoin, cudaEventDisableTiming);

    cudaEventRecord(eFork, 0);
    cudaStreamWaitEvent(s2, eFork, 0);

    __half* u3h = (__half*)(U + (size_t)3 * NN * 64);

    // ---- chain B (s2): precompute -> full GEMM ----
    k_preA<<<(2 * 16384 + TB - 1) / TB, TB, 0, s2>>>(W2s, W2n, Wfc);
    k_preB<<<(3 * 16384 + TB - 1) / TB, TB, 0, s2>>>(W1s, W1n);
    k_preC<<<(4 * 8192 + TB - 1) / TB, TB, 0, s2>>>(W0s, W0n);
    cudaEventRecord(ePre, s2);
    {
        dim3 gG(2, (NN + 127) / 128);
        k_wgemm<<<gG, 256, smem_bytes, s2>>>(x, CTh, CTl, U, u3h, NN);
    }
    cudaEventRecord(eJoin, s2);

    // ---- chain A (default stream): CSR build, then rvec (uses chain-A slack) ----
    k_zero_counts<<<nblk_n, TB>>>();
    k_count<<<nblk_e, TB>>>(edst);
    k_scan_tiles<<<ntiles, 1024>>>();
    k_scan_sums<<<1, 64>>>(ntiles);
    k_scan_fix<<<nblk_n, TB>>>();
    k_fill<<<nblk_e, TB>>>(esrc, edst);
    cudaStreamWaitEvent(0, ePre, 0);
    k_rvec<<<24, 256>>>(b0, b1, b2, bfc, Wfc);

    // join
    cudaStreamWaitEvent(0, eJoin, 0);

    // ---- Horner aggregation (fp16 srcs, fp16-native accumulation) ----
    const float4* u0 = (const float4*)U;
    const float4* u1 = (const float4*)(U + (size_t)1 * NN * 64);
    const float4* u2 = (const float4*)(U + (size_t)2 * NN * 64);
    __half* s2h = sh;
    __half* s1h = sh + (size_t)NN * 64;
    int gblk = (NN * 8 + TB - 1) / TB;
    k_gather64h<<<gblk, TB>>>((const uint4*)u3h, u2, s2h, 1);
    k_gather64h<<<gblk, TB>>>((const uint4*)s2h, u1, s1h, 0);
    k_gather64h<<<gblk, TB>>>((const uint4*)s1h, u0, out, 2);
}

// round 16
// speedup vs baseline: 1.3564x; 1.0131x over previous
#include <cuda_runtime.h>
#include <cuda_bf16.h>
#include <cuda_fp16.h>
#include <math.h>
#include <cstdint>

#define NN 50000
#define NE 800000
#define INF 128
#define HID 256
#define NCLS 64

// ---------------- device scratch ----------------
__device__ int   g_deg[NN];
__device__ int   g_cursor[NN];
__device__ int   g_off[NN + 1];
__device__ int   g_csr[NE];
__device__ float g_invdeg[NN];
__device__ int   g_tsum[64];
// U chunks u0,u1,u2 fp32; chunk3 region reused as fp16 u3
__device__ __align__(16) float g_U[(size_t)4 * NN * 64];
__device__ __align__(16) __half g_sh[(size_t)2 * NN * 64];   // s2h, s1h (fp16)
// g_pre layout: Us=0, Un=16384, Q0=32768, Q1=49152, Q2=65536
__device__ __align__(16) float g_pre[5 * 256 * 64];
__device__ __align__(16) __nv_bfloat16 g_CTh[256 * 128];   // Cbig^T hi [n][k]
__device__ __align__(16) __nv_bfloat16 g_CTl[256 * 128];   // Cbig^T lo
__device__ float g_r[3 * 64];
__device__ float g_e1[NN];
__device__ float g_e2[NN];

// ---------------- CSR build ----------------
__global__ void k_zero_counts() {
    int i = blockIdx.x * blockDim.x + threadIdx.x;
    if (i < NN) { g_deg[i] = 0; g_cursor[i] = 0; }
}

__global__ void k_count(const int* __restrict__ dst) {
    int e = blockIdx.x * blockDim.x + threadIdx.x;
    if (e < NE) atomicAdd(&g_deg[dst[e]], 1);
}

__global__ void k_scan_tiles() {
    __shared__ int sh[1024];
    int t = threadIdx.x;
    int i = blockIdx.x * 1024 + t;
    int v = (i < NN) ? g_deg[i] : 0;
    sh[t] = v;
    __syncthreads();
    for (int d = 1; d < 1024; d <<= 1) {
        int x = 0;
        if (t >= d) x = sh[t - d];
        __syncthreads();
        sh[t] += x;
        __syncthreads();
    }
    if (i < NN) g_off[i] = sh[t] - v;
    if (t == 1023) g_tsum[blockIdx.x] = sh[t];
}

__global__ void k_scan_sums(int ntiles) {
    __shared__ int sh[64];
    int t = threadIdx.x;
    int v = (t < ntiles) ? g_tsum[t] : 0;
    sh[t] = v;
    __syncthreads();
    for (int d = 1; d < 64; d <<= 1) {
        int x = 0;
        if (t >= d) x = sh[t - d];
        __syncthreads();
        sh[t] += x;
        __syncthreads();
    }
    if (t < ntiles) g_tsum[t] = sh[t] - v;
}

__global__ void k_scan_fix() {
    int i = blockIdx.x * blockDim.x + threadIdx.x;
    if (i < NN) {
        g_off[i] += g_tsum[i >> 10];
        int d = g_deg[i];
        g_invdeg[i] = 1.0f / fmaxf((float)d, 1.0f);
        g_e1[i] = (d > 0) ? 1.0f : 0.0f;
    }
    if (i == 0) g_off[NN] = NE;
}

__global__ void k_fill(const int* __restrict__ src, const int* __restrict__ dst) {
    int e = blockIdx.x * blockDim.x + threadIdx.x;
    if (e < NE) {
        int d = dst[e];
        int pos = g_off[d] + atomicAdd(&g_cursor[d], 1);
        g_csr[pos] = src[e];
    }
}

// ---------------- fused precompute stages ----------------
__global__ void k_preA(const float* __restrict__ W2s, const float* __restrict__ W2n,
                       const float* __restrict__ Wfc) {
    int idx = blockIdx.x * blockDim.x + threadIdx.x;
    if (idx >= 2 * 16384) return;
    int which = idx >> 14;
    int j = idx & 16383;
    int r = j >> 6, c = j & 63;
    const float* A = which ? W2n : W2s;
    float acc = 0.f;
    #pragma unroll 8
    for (int k = 0; k < 256; ++k) acc += A[r * 256 + k] * Wfc[k * 64 + c];
    g_pre[which * 16384 + j] = acc;
}

__global__ void k_preB(const float* __restrict__ W1s, const float* __restrict__ W1n) {
    int idx = blockIdx.x * blockDim.x + threadIdx.x;
    if (idx >= 3 * 16384) return;
    int which = idx / 16384;
    int j = idx % 16384;
    int r = j >> 6, c = j & 63;
    const float* Us = g_pre;
    const float* Un = g_pre + 16384;
    float acc = 0.f;
    if (which == 0) {
        #pragma unroll 8
        for (int k = 0; k < 256; ++k) acc += W1s[r * 256 + k] * Us[k * 64 + c];
    } else if (which == 1) {
        #pragma unroll 8
        for (int k = 0; k < 256; ++k)
            acc += W1n[r * 256 + k] * Us[k * 64 + c] + W1s[r * 256 + k] * Un[k * 64 + c];
    } else {
        #pragma unroll 8
        for (int k = 0; k < 256; ++k) acc += W1n[r * 256 + k] * Un[k * 64 + c];
    }
    g_pre[32768 + which * 16384 + j] = acc;
}

__global__ void k_preC(const float* __restrict__ W0s, const float* __restrict__ W0n) {
    int idx = blockIdx.x * blockDim.x + threadIdx.x;
    if (idx >= 4 * 8192) return;
    int chunk = idx >> 13;
    int j = idx & 8191;
    int r = j >> 6, c = j & 63;
    const float* Q0 = g_pre + 32768;
    const float* Q1 = g_pre + 49152;
    const float* Q2 = g_pre + 65536;
    float acc = 0.f;
    if (chunk == 0) {
        #pragma unroll 8
        for (int k = 0; k < 256; ++k) acc += W0s[r * 256 + k] * Q0[k * 64 + c];
    } else if (chunk == 1) {
        #pragma unroll 8
        for (int k = 0; k < 256; ++k)
            acc += W0n[r * 256 + k] * Q0[k * 64 + c] + W0s[r * 256 + k] * Q1[k * 64 + c];
    } else if (chunk == 2) {
        #pragma unroll 8
        for (int k = 0; k < 256; ++k)
            acc += W0n[r * 256 + k] * Q1[k * 64 + c] + W0s[r * 256 + k] * Q2[k * 64 + c];
    } else {
        #pragma unroll 8
        for (int k = 0; k < 256; ++k) acc += W0n[r * 256 + k] * Q2[k * 64 + c];
    }
    __nv_bfloat16 h = __float2bfloat16(acc);
    g_CTh[chunk * 8192 + c * 128 + r] = h;
    g_CTl[chunk * 8192 + c * 128 + r] = __float2bfloat16(acc - __bfloat162float(h));
}

// warp-parallel rvec: one warp per output element (192 outputs)
__global__ void k_rvec(const float* __restrict__ b0, const float* __restrict__ b1,
                       const float* __restrict__ b2, const float* __restrict__ bfc,
                       const float* __restrict__ Wfc) {
    const float* Us = g_pre;
    const float* Un = g_pre + 16384;
    const float* Q0 = g_pre + 32768;
    const float* Q1 = g_pre + 49152;
    const float* Q2 = g_pre + 65536;
    int gw = (blockIdx.x * blockDim.x + threadIdx.x) >> 5;
    int lane = threadIdx.x & 31;
    if (gw >= 192) return;
    int which = gw / 64, c = gw % 64;
    float acc = 0.f;
    if (which == 0) {
        #pragma unroll
        for (int k = lane; k < 256; k += 32)
            acc += b0[k] * Q0[k * 64 + c] + b1[k] * Us[k * 64 + c] + b2[k] * Wfc[k * 64 + c];
    } else if (which == 1) {
        #pragma unroll
        for (int k = lane; k < 256; k += 32)
            acc += b0[k] * Q1[k * 64 + c] + b1[k] * Un[k * 64 + c];
    } else {
        #pragma unroll
        for (int k = lane; k < 256; k += 32)
            acc += b0[k] * Q2[k * 64 + c];
    }
    #pragma unroll
    for (int o = 16; o > 0; o >>= 1)
        acc += __shfl_xor_sync(0xFFFFFFFFu, acc, o);
    if (lane == 0) {
        if (which == 0) acc += bfc[c];
        g_r[gw] = acc;
    }
}

// ---------------- 64-dim mean gather, fp16 src, fp16-native accumulation ------
__global__ void k_gather64h(const uint4* __restrict__ src,
                            const float4* __restrict__ add,
                            void* __restrict__ out, int mode) {
    int gtid = blockIdx.x * blockDim.x + threadIdx.x;
    int node = gtid >> 3;
    int c = gtid & 7;
    if (node >= NN) return;
    int s = g_off[node], e = g_off[node + 1];
    float acc[8] = {0.f, 0.f, 0.f, 0.f, 0.f, 0.f, 0.f, 0.f};
    float ecnt = 0.f;
    int idx = s;
    for (; idx + 8 <= e; idx += 8) {
        int n[8];
        #pragma unroll
        for (int j = 0; j < 8; ++j) n[j] = g_csr[idx + j];
        uint4 v[8];
        #pragma unroll
        for (int j = 0; j < 8; ++j) v[j] = src[(size_t)n[j] * 8 + c];
        if (mode == 1 && c == 0) {
            #pragma unroll
            for (int j = 0; j < 8; ++j) ecnt += (g_deg[n[j]] > 0) ? 1.f : 0.f;
        }
        __half2 hA[4], hB[4];
        {
            const __half2* h0 = (const __half2*)&v[0];
            const __half2* h1 = (const __half2*)&v[1];
            #pragma unroll
            for (int i = 0; i < 4; ++i) { hA[i] = h0[i]; hB[i] = h1[i]; }
        }
        #pragma unroll
        for (int j = 2; j < 8; j += 2) {
            const __half2* hj0 = (const __half2*)&v[j];
            const __half2* hj1 = (const __half2*)&v[j + 1];
            #pragma unroll
            for (int i = 0; i < 4; ++i) {
                hA[i] = __hadd2(hA[i], hj0[i]);
                hB[i] = __hadd2(hB[i], hj1[i]);
            }
        }
        #pragma unroll
        for (int i = 0; i < 4; ++i) {
            float2 fa = __half22float2(hA[i]);
            float2 fb = __half22float2(hB[i]);
            acc[2 * i]     += fa.x + fb.x;
            acc[2 * i + 1] += fa.y + fb.y;
        }
    }
    for (; idx < e; ++idx) {
        int sn = g_csr[idx];
        uint4 v = src[(size_t)sn * 8 + c];
        if (mode == 1 && c == 0) ecnt += (g_deg[sn] > 0) ? 1.f : 0.f;
        const __half2* h = (const __half2*)&v;
        #pragma unroll
        for (int i = 0; i < 4; ++i) {
            float2 f = __half22float2(h[i]);
            acc[2 * i] += f.x;
            acc[2 * i + 1] += f.y;
        }
    }
    float w = g_invdeg[node];
    if (mode == 1 && c == 0) g_e2[node] = ecnt * w;
    float4 d0 = add[(size_t)node * 16 + 2 * c];
    float4 d1 = add[(size_t)node * 16 + 2 * c + 1];
    float f[8];
    f[0] = d0.x + acc[0] * w;
    f[1] = d0.y + acc[1] * w;
    f[2] = d0.z + acc[2] * w;
    f[3] = d0.w + acc[3] * w;
    f[4] = d1.x + acc[4] * w;
    f[5] = d1.y + acc[5] * w;
    f[6] = d1.z + acc[6] * w;
    f[7] = d1.w + acc[7] * w;
    if (mode == 2) {
        float a = g_e1[node], b = g_e2[node];
        #pragma unroll
        for (int i = 0; i < 8; ++i) {
            int col = c * 8 + i;
            f[i] += g_r[col] + a * g_r[64 + col] + b * g_r[128 + col];
        }
        float4* o = (float4*)out;
        o[(size_t)node * 16 + 2 * c]     = make_float4(f[0], f[1], f[2], f[3]);
        o[(size_t)node * 16 + 2 * c + 1] = make_float4(f[4], f[5], f[6], f[7]);
    } else {
        uint4 hv;
        __half2 h0 = __floats2half2_rn(f[0], f[1]);
        __half2 h1 = __floats2half2_rn(f[2], f[3]);
        __half2 h2 = __floats2half2_rn(f[4], f[5]);
        __half2 h3 = __floats2half2_rn(f[6], f[7]);
        hv.x = *(uint32_t*)&h0; hv.y = *(uint32_t*)&h1;
        hv.z = *(uint32_t*)&h2; hv.w = *(uint32_t*)&h3;
        ((uint4*)out)[(size_t)node * 8 + c] = hv;
    }
}

// ---------------- mma.sync bf16 split GEMM, single-pass fused mainloop --------
#define LDK 136
#define SM_AH 0
#define SM_AL (128 * LDK)
#define SM_BH (2 * 128 * LDK)
#define SM_BL (3 * 128 * LDK)
#define SM_HALVES (4 * 128 * LDK)

#define MMA16816(c, a, b0_, b1_) \
    asm volatile("mma.sync.aligned.m16n8k16.row.col.f32.bf16.bf16.f32 " \
        "{%0,%1,%2,%3}, {%4,%5,%6,%7}, {%8,%9}, {%0,%1,%2,%3};" \
        : "+f"((c)[0]), "+f"((c)[1]), "+f"((c)[2]), "+f"((c)[3]) \
        : "r"((a)[0]), "r"((a)[1]), "r"((a)[2]), "r"((a)[3]), \
          "r"(b0_), "r"(b1_))

#define LDSM4(r0, r1, r2, r3, addr) \
    asm volatile("ldmatrix.sync.aligned.m8n8.x4.shared.b16 {%0,%1,%2,%3}, [%4];" \
        : "=r"(r0), "=r"(r1), "=r"(r2), "=r"(r3) : "r"(addr))

#define CPASYNC16(dst, src) \
    asm volatile("cp.async.ca.shared.global [%0], [%1], 16;" \
        :: "r"(dst), "l"(src) : "memory")

__global__ __launch_bounds__(256, 1)
void k_wgemm(const float* __restrict__ x, const __nv_bfloat16* __restrict__ CTh,
             const __nv_bfloat16* __restrict__ CTl, float* __restrict__ U,
             __half* __restrict__ u3h, int M) {
    extern __shared__ __nv_bfloat16 sm[];
    __nv_bfloat16* Ah = sm + SM_AH;
    __nv_bfloat16* Al = sm + SM_AL;
    __nv_bfloat16* Bh = sm + SM_BH;
    __nv_bfloat16* Bl = sm + SM_BL;

    const int tid = threadIdx.x;
    const int bm = blockIdx.y * 128;
    const int colbase = blockIdx.x * 128;
    const __nv_bfloat16* cth = CTh + (size_t)colbase * 128;
    const __nv_bfloat16* ctl = CTl + (size_t)colbase * 128;

    const int r = tid >> 1;
    const int half = tid & 1;

    // ---- stage B via cp.async (fire-and-forget, overlaps A conversion) ----
    {
        const char* shp = (const char*)(cth + (size_t)r * 128 + half * 64);
        const char* slp = (const char*)(ctl + (size_t)r * 128 + half * 64);
        uint32_t dh = (uint32_t)__cvta_generic_to_shared(Bh + r * LDK + half * 64);
        uint32_t dl = (uint32_t)__cvta_generic_to_shared(Bl + r * LDK + half * 64);
        #pragma unroll
        for (int j = 0; j < 8; ++j) {
            CPASYNC16(dh + 16 * j, shp + 16 * j);
            CPASYNC16(dl + 16 * j, slp + 16 * j);
        }
        asm volatile("cp.async.commit_group;" ::: "memory");
    }

    // ---- stage A: two rounds of 8 batched loads (lower peak regs) ----
    {
        int grow = bm + r;
        const float4* xr = (const float4*)(x + (size_t)grow * 128 + half * 64);
        __nv_bfloat16* ah = Ah + r * LDK + half * 64;
        __nv_bfloat16* al = Al + r * LDK + half * 64;
        #pragma unroll
        for (int rd = 0; rd < 2; ++rd) {
            float4 v[8];
            if (grow < M) {
                #pragma unroll
                for (int j = 0; j < 8; ++j) v[j] = xr[rd * 8 + j];
            } else {
                #pragma unroll
                for (int j = 0; j < 8; ++j) v[j] = make_float4(0.f, 0.f, 0.f, 0.f);
            }
            #pragma unroll
            for (int j = 0; j < 4; ++j) {
                float f[8];
                float4 v0 = v[2 * j], v1 = v[2 * j + 1];
                f[0] = v0.x; f[1] = v0.y; f[2] = v0.z; f[3] = v0.w;
                f[4] = v1.x; f[5] = v1.y; f[6] = v1.z; f[7] = v1.w;
                uint32_t hp[4], lp[4];
                #pragma unroll
                for (int e = 0; e < 4; ++e) {
                    __nv_bfloat16 h0 = __float2bfloat16(f[2 * e]);
                    __nv_bfloat16 h1 = __float2bfloat16(f[2 * e + 1]);
                    float l0 = f[2 * e]     - __bfloat162float(h0);
                    float l1 = f[2 * e + 1] - __bfloat162float(h1);
                    __nv_bfloat162 hh = __halves2bfloat162(h0, h1);
                    __nv_bfloat162 lv = __halves2bfloat162(__float2bfloat16(l0),
                                                           __float2bfloat16(l1));
                    hp[e] = *(uint32_t*)&hh;
                    lp[e] = *(uint32_t*)&lv;
                }
                *(uint4*)(ah + rd * 32 + 8 * j) = make_uint4(hp[0], hp[1], hp[2], hp[3]);
                *(uint4*)(al + rd * 32 + 8 * j) = make_uint4(lp[0], lp[1], lp[2], lp[3]);
            }
        }
    }
    asm volatile("cp.async.wait_group 0;" ::: "memory");
    __syncthreads();

    const int w = tid >> 5, lane = tid & 31;
    const int wm = (w >> 2) * 64;
    const int wn = (w & 3) * 32;
    const int lr = lane >> 2;
    const int lc = (lane & 3) * 2;
    const int g  = lane >> 3, gl = lane & 7;
    const int a_r = (g & 1) * 8 + gl;
    const int a_c = (g >> 1) * 8;
    const int b_r = (g >> 1) * 8 + gl;
    const int b_c = (g & 1) * 8;

    float acc[4][4][4];
    #pragma unroll
    for (int i = 0; i < 4; ++i)
        #pragma unroll
        for (int j = 0; j < 4; ++j)
            #pragma unroll
            for (int e = 0; e < 4; ++e) acc[i][j][e] = 0.f;

    // single-pass mainloop: load each fragment once, issue all 3 products
    #pragma unroll
    for (int ks = 0; ks < 8; ++ks) {
        int kb = ks * 16;
        uint32_t ah[4][4], al[4][4];
        #pragma unroll
        for (int fm = 0; fm < 4; ++fm) {
            uint32_t addr_h = (uint32_t)__cvta_generic_to_shared(
                &Ah[(wm + fm * 16 + a_r) * LDK + kb + a_c]);
            LDSM4(ah[fm][0], ah[fm][1], ah[fm][2], ah[fm][3], addr_h);
            uint32_t addr_l = (uint32_t)__cvta_generic_to_shared(
                &Al[(wm + fm * 16 + a_r) * LDK + kb + a_c]);
            LDSM4(al[fm][0], al[fm][1], al[fm][2], al[fm][3], addr_l);
        }
        uint32_t bh[4][2], bl[4][2];
        #pragma unroll
        for (int p = 0; p < 2; ++p) {
            uint32_t addr_h = (uint32_t)__cvta_generic_to_shared(
                &Bh[(wn + p * 16 + b_r) * LDK + kb + b_c]);
            LDSM4(bh[2 * p][0], bh[2 * p][1], bh[2 * p + 1][0], bh[2 * p + 1][1], addr_h);
            uint32_t addr_l = (uint32_t)__cvta_generic_to_shared(
                &Bl[(wn + p * 16 + b_r) * LDK + kb + b_c]);
            LDSM4(bl[2 * p][0], bl[2 * p][1], bl[2 * p + 1][0], bl[2 * p + 1][1], addr_l);
        }
        #pragma unroll
        for (int fn = 0; fn < 4; ++fn)
            #pragma unroll
            for (int fm = 0; fm < 4; ++fm) {
                MMA16816(acc[fm][fn], ah[fm], bh[fn][0], bh[fn][1]);
                MMA16816(acc[fm][fn], ah[fm], bl[fn][0], bl[fn][1]);
                MMA16816(acc[fm][fn], al[fm], bh[fn][0], bh[fn][1]);
            }
    }

    #pragma unroll
    for (int fm = 0; fm < 4; ++fm) {
        int r0 = bm + wm + fm * 16 + lr;
        int r1 = r0 + 8;
        #pragma unroll
        for (int fn = 0; fn < 4; ++fn) {
            int col = colbase + wn + fn * 8 + lc;
            int chunk = col >> 6, off = col & 63;
            if (chunk == 3) {
                if (r0 < M) {
                    __half2 h = __floats2half2_rn(acc[fm][fn][0], acc[fm][fn][1]);
                    *(__half2*)(u3h + (size_t)r0 * 64 + off) = h;
                }
                if (r1 < M) {
                    __half2 h = __floats2half2_rn(acc[fm][fn][2], acc[fm][fn][3]);
                    *(__half2*)(u3h + (size_t)r1 * 64 + off) = h;
                }
            } else {
                float* dst = U + (size_t)chunk * NN * 64 + off;
                if (r0 < M)
                    *(float2*)(dst + (size_t)r0 * 64) =
                        make_float2(acc[fm][fn][0], acc[fm][fn][1]);
                if (r1 < M)
                    *(float2*)(dst + (size_t)r1 * 64) =
                        make_float2(acc[fm][fn][2], acc[fm][fn][3]);
            }
        }
    }
}

// ---------------- launch ----------------
extern "C" void kernel_launch(void* const* d_in, const int* in_sizes, int n_in,
                              void* d_out, int out_size) {
    const float* x    = (const float*)d_in[0];
    const int*   esrc = (const int*)d_in[1];
    const int*   edst = (const int*)d_in[2];
    const float* W0s  = (const float*)d_in[3];
    const float* W0n  = (const float*)d_in[4];
    const float* b0   = (const float*)d_in[5];
    const float* W1s  = (const float*)d_in[6];
    const float* W1n  = (const float*)d_in[7];
    const float* b1   = (const float*)d_in[8];
    const float* W2s  = (const float*)d_in[9];
    const float* W2n  = (const float*)d_in[10];
    const float* b2   = (const float*)d_in[11];
    const float* Wfc  = (const float*)d_in[12];
    const float* bfc  = (const float*)d_in[13];
    float* out = (float*)d_out;

    float *U;
    __half *sh;
    __nv_bfloat16 *CTh, *CTl;
    cudaGetSymbolAddress((void**)&U,   g_U);
    cudaGetSymbolAddress((void**)&sh,  g_sh);
    cudaGetSymbolAddress((void**)&CTh, g_CTh);
    cudaGetSymbolAddress((void**)&CTl, g_CTl);

    const int TB = 256;
    int nblk_n = (NN + TB - 1) / TB;
    int nblk_e = (NE + TB - 1) / TB;
    int ntiles = (NN + 1023) / 1024;

    size_t smem_bytes = (size_t)SM_HALVES * sizeof(__nv_bfloat16);
    cudaFuncSetAttribute(k_wgemm, cudaFuncAttributeMaxDynamicSharedMemorySize,
                         (int)smem_bytes);

    cudaStream_t s2;
    cudaStreamCreateWithFlags(&s2, cudaStreamNonBlocking);
    cudaEvent_t eFork, ePre, eJoin;
    cudaEventCreateWithFlags(&eFork, cudaEventDisableTiming);
    cudaEventCreateWithFlags(&ePre,  cudaEventDisableTiming);
    cudaEventCreateWithFlags(&eJoin, cudaEventDisableTiming);

    cudaEventRecord(eFork, 0);
    cudaStreamWaitEvent(s2, eFork, 0);

    __half* u3h = (__half*)(U + (size_t)3 * NN * 64);

    // ---- chain B (s2): precompute -> full GEMM ----
    k_preA<<<(2 * 16384 + TB - 1) / TB, TB, 0, s2>>>(W2s, W2n, Wfc);
    k_preB<<<(3 * 16384 + TB - 1) / TB, TB, 0, s2>>>(W1s, W1n);
    k_preC<<<(4 * 8192 + TB - 1) / TB, TB, 0, s2>>>(W0s, W0n);
    cudaEventRecord(ePre, s2);
    {
        dim3 gG(2, (NN + 127) / 128);
        k_wgemm<<<gG, 256, smem_bytes, s2>>>(x, CTh, CTl, U, u3h, NN);
    }
    cudaEventRecord(eJoin, s2);

    // ---- chain A (default stream): CSR build, then rvec ----
    k_zero_counts<<<nblk_n, TB>>>();
    k_count<<<nblk_e, TB>>>(edst);
    k_scan_tiles<<<ntiles, 1024>>>();
    k_scan_sums<<<1, 64>>>(ntiles);
    k_scan_fix<<<nblk_n, TB>>>();
    k_fill<<<nblk_e, TB>>>(esrc, edst);
    cudaStreamWaitEvent(0, ePre, 0);
    k_rvec<<<24, 256>>>(b0, b1, b2, bfc, Wfc);

    // join
    cudaStreamWaitEvent(0, eJoin, 0);

    // ---- Horner aggregation (fp16 srcs, fp16-native accumulation) ----
    const float4* u0 = (const float4*)U;
    const float4* u1 = (const float4*)(U + (size_t)1 * NN * 64);
    const float4* u2 = (const float4*)(U + (size_t)2 * NN * 64);
    __half* s2h = sh;
    __half* s1h = sh + (size_t)NN * 64;
    int gblk = (NN * 8 + TB - 1) / TB;
    k_gather64h<<<gblk, TB>>>((const uint4*)u3h, u2, s2h, 1);
    k_gather64h<<<gblk, TB>>>((const uint4*)s2h, u1, s1h, 0);
    k_gather64h<<<gblk, TB>>>((const uint4*)s1h, u0, out, 2);
}

// round 17
// speedup vs baseline: 1.4201x; 1.0469x over previous
#include <cuda_runtime.h>
#include <cuda_bf16.h>
#include <cuda_fp16.h>
#include <math.h>
#include <cstdint>

#define NN 50000
#define NE 800000
#define INF 128
#define HID 256
#define NCLS 64

// ---------------- device scratch ----------------
__device__ int   g_deg[NN];
__device__ int   g_cursor[NN];
__device__ int   g_off[NN + 1];
__device__ int   g_csr[NE];
__device__ float g_invdeg[NN];
__device__ int   g_tsum[64];
// U chunks u0,u1,u2 fp32; chunk3 region reused as fp16 u3
__device__ __align__(16) float g_U[(size_t)4 * NN * 64];
__device__ __align__(16) __half g_sh[(size_t)2 * NN * 64];   // s2h, s1h (fp16)
// g_pre layout: Us=0, Un=16384, Q0=32768, Q1=49152, Q2=65536
__device__ __align__(16) float g_pre[5 * 256 * 64];
__device__ __align__(16) __nv_bfloat16 g_CTh[256 * 128];   // Cbig^T hi [n][k]
__device__ __align__(16) __nv_bfloat16 g_CTl[256 * 128];   // Cbig^T lo
__device__ float g_r[3 * 64];
__device__ float g_e1[NN];
__device__ float g_e2[NN];

// ---------------- CSR build ----------------
__global__ void k_zero_counts() {
    int i = blockIdx.x * blockDim.x + threadIdx.x;
    if (i < NN) { g_deg[i] = 0; g_cursor[i] = 0; }
}

__global__ void k_count(const int* __restrict__ dst) {
    int e = blockIdx.x * blockDim.x + threadIdx.x;
    if (e < NE) atomicAdd(&g_deg[dst[e]], 1);
}

__global__ void k_scan_tiles() {
    __shared__ int sh[1024];
    int t = threadIdx.x;
    int i = blockIdx.x * 1024 + t;
    int v = (i < NN) ? g_deg[i] : 0;
    sh[t] = v;
    __syncthreads();
    for (int d = 1; d < 1024; d <<= 1) {
        int x = 0;
        if (t >= d) x = sh[t - d];
        __syncthreads();
        sh[t] += x;
        __syncthreads();
    }
    if (i < NN) g_off[i] = sh[t] - v;
    if (t == 1023) g_tsum[blockIdx.x] = sh[t];
}

__global__ void k_scan_sums(int ntiles) {
    __shared__ int sh[64];
    int t = threadIdx.x;
    int v = (t < ntiles) ? g_tsum[t] : 0;
    sh[t] = v;
    __syncthreads();
    for (int d = 1; d < 64; d <<= 1) {
        int x = 0;
        if (t >= d) x = sh[t - d];
        __syncthreads();
        sh[t] += x;
        __syncthreads();
    }
    if (t < ntiles) g_tsum[t] = sh[t] - v;
}

__global__ void k_scan_fix() {
    int i = blockIdx.x * blockDim.x + threadIdx.x;
    if (i < NN) {
        g_off[i] += g_tsum[i >> 10];
        int d = g_deg[i];
        g_invdeg[i] = 1.0f / fmaxf((float)d, 1.0f);
        g_e1[i] = (d > 0) ? 1.0f : 0.0f;
    }
    if (i == 0) g_off[NN] = NE;
}

__global__ void k_fill(const int* __restrict__ src, const int* __restrict__ dst) {
    int e = blockIdx.x * blockDim.x + threadIdx.x;
    if (e < NE) {
        int d = dst[e];
        int pos = g_off[d] + atomicAdd(&g_cursor[d], 1);
        g_csr[pos] = src[e];
    }
}

// ---------------- fused precompute stages ----------------
__global__ void k_preA(const float* __restrict__ W2s, const float* __restrict__ W2n,
                       const float* __restrict__ Wfc) {
    int idx = blockIdx.x * blockDim.x + threadIdx.x;
    if (idx >= 2 * 16384) return;
    int which = idx >> 14;
    int j = idx & 16383;
    int r = j >> 6, c = j & 63;
    const float* A = which ? W2n : W2s;
    float acc = 0.f;
    #pragma unroll 8
    for (int k = 0; k < 256; ++k) acc += A[r * 256 + k] * Wfc[k * 64 + c];
    g_pre[which * 16384 + j] = acc;
}

__global__ void k_preB(const float* __restrict__ W1s, const float* __restrict__ W1n) {
    int idx = blockIdx.x * blockDim.x + threadIdx.x;
    if (idx >= 3 * 16384) return;
    int which = idx / 16384;
    int j = idx % 16384;
    int r = j >> 6, c = j & 63;
    const float* Us = g_pre;
    const float* Un = g_pre + 16384;
    float acc = 0.f;
    if (which == 0) {
        #pragma unroll 8
        for (int k = 0; k < 256; ++k) acc += W1s[r * 256 + k] * Us[k * 64 + c];
    } else if (which == 1) {
        #pragma unroll 8
        for (int k = 0; k < 256; ++k)
            acc += W1n[r * 256 + k] * Us[k * 64 + c] + W1s[r * 256 + k] * Un[k * 64 + c];
    } else {
        #pragma unroll 8
        for (int k = 0; k < 256; ++k) acc += W1n[r * 256 + k] * Un[k * 64 + c];
    }
    g_pre[32768 + which * 16384 + j] = acc;
}

__global__ void k_preC(const float* __restrict__ W0s, const float* __restrict__ W0n) {
    int idx = blockIdx.x * blockDim.x + threadIdx.x;
    if (idx >= 4 * 8192) return;
    int chunk = idx >> 13;
    int j = idx & 8191;
    int r = j >> 6, c = j & 63;
    const float* Q0 = g_pre + 32768;
    const float* Q1 = g_pre + 49152;
    const float* Q2 = g_pre + 65536;
    float acc = 0.f;
    if (chunk == 0) {
        #pragma unroll 8
        for (int k = 0; k < 256; ++k) acc += W0s[r * 256 + k] * Q0[k * 64 + c];
    } else if (chunk == 1) {
        #pragma unroll 8
        for (int k = 0; k < 256; ++k)
            acc += W0n[r * 256 + k] * Q0[k * 64 + c] + W0s[r * 256 + k] * Q1[k * 64 + c];
    } else if (chunk == 2) {
        #pragma unroll 8
        for (int k = 0; k < 256; ++k)
            acc += W0n[r * 256 + k] * Q1[k * 64 + c] + W0s[r * 256 + k] * Q2[k * 64 + c];
    } else {
        #pragma unroll 8
        for (int k = 0; k < 256; ++k) acc += W0n[r * 256 + k] * Q2[k * 64 + c];
    }
    __nv_bfloat16 h = __float2bfloat16(acc);
    g_CTh[chunk * 8192 + c * 128 + r] = h;
    g_CTl[chunk * 8192 + c * 128 + r] = __float2bfloat16(acc - __bfloat162float(h));
}

// warp-parallel rvec: one warp per output element (192 outputs)
__global__ void k_rvec(const float* __restrict__ b0, const float* __restrict__ b1,
                       const float* __restrict__ b2, const float* __restrict__ bfc,
                       const float* __restrict__ Wfc) {
    const float* Us = g_pre;
    const float* Un = g_pre + 16384;
    const float* Q0 = g_pre + 32768;
    const float* Q1 = g_pre + 49152;
    const float* Q2 = g_pre + 65536;
    int gw = (blockIdx.x * blockDim.x + threadIdx.x) >> 5;
    int lane = threadIdx.x & 31;
    if (gw >= 192) return;
    int which = gw / 64, c = gw % 64;
    float acc = 0.f;
    if (which == 0) {
        #pragma unroll
        for (int k = lane; k < 256; k += 32)
            acc += b0[k] * Q0[k * 64 + c] + b1[k] * Us[k * 64 + c] + b2[k] * Wfc[k * 64 + c];
    } else if (which == 1) {
        #pragma unroll
        for (int k = lane; k < 256; k += 32)
            acc += b0[k] * Q1[k * 64 + c] + b1[k] * Un[k * 64 + c];
    } else {
        #pragma unroll
        for (int k = lane; k < 256; k += 32)
            acc += b0[k] * Q2[k * 64 + c];
    }
    #pragma unroll
    for (int o = 16; o > 0; o >>= 1)
        acc += __shfl_xor_sync(0xFFFFFFFFu, acc, o);
    if (lane == 0) {
        if (which == 0) acc += bfc[c];
        g_r[gw] = acc;
    }
}

// ---------------- 64-dim mean gather, fp16 src, fp16-native accumulation ------
__global__ void k_gather64h(const uint4* __restrict__ src,
                            const float4* __restrict__ add,
                            void* __restrict__ out, int mode) {
    int gtid = blockIdx.x * blockDim.x + threadIdx.x;
    int node = gtid >> 3;
    int c = gtid & 7;
    if (node >= NN) return;
    int s = g_off[node], e = g_off[node + 1];
    float acc[8] = {0.f, 0.f, 0.f, 0.f, 0.f, 0.f, 0.f, 0.f};
    float ecnt = 0.f;
    int idx = s;
    for (; idx + 8 <= e; idx += 8) {
        int n[8];
        #pragma unroll
        for (int j = 0; j < 8; ++j) n[j] = g_csr[idx + j];
        uint4 v[8];
        #pragma unroll
        for (int j = 0; j < 8; ++j) v[j] = src[(size_t)n[j] * 8 + c];
        if (mode == 1 && c == 0) {
            #pragma unroll
            for (int j = 0; j < 8; ++j) ecnt += (g_deg[n[j]] > 0) ? 1.f : 0.f;
        }
        __half2 hA[4], hB[4];
        {
            const __half2* h0 = (const __half2*)&v[0];
            const __half2* h1 = (const __half2*)&v[1];
            #pragma unroll
            for (int i = 0; i < 4; ++i) { hA[i] = h0[i]; hB[i] = h1[i]; }
        }
        #pragma unroll
        for (int j = 2; j < 8; j += 2) {
            const __half2* hj0 = (const __half2*)&v[j];
            const __half2* hj1 = (const __half2*)&v[j + 1];
            #pragma unroll
            for (int i = 0; i < 4; ++i) {
                hA[i] = __hadd2(hA[i], hj0[i]);
                hB[i] = __hadd2(hB[i], hj1[i]);
            }
        }
        #pragma unroll
        for (int i = 0; i < 4; ++i) {
            float2 fa = __half22float2(hA[i]);
            float2 fb = __half22float2(hB[i]);
            acc[2 * i]     += fa.x + fb.x;
            acc[2 * i + 1] += fa.y + fb.y;
        }
    }
    for (; idx < e; ++idx) {
        int sn = g_csr[idx];
        uint4 v = src[(size_t)sn * 8 + c];
        if (mode == 1 && c == 0) ecnt += (g_deg[sn] > 0) ? 1.f : 0.f;
        const __half2* h = (const __half2*)&v;
        #pragma unroll
        for (int i = 0; i < 4; ++i) {
            float2 f = __half22float2(h[i]);
            acc[2 * i] += f.x;
            acc[2 * i + 1] += f.y;
        }
    }
    float w = g_invdeg[node];
    if (mode == 1 && c == 0) g_e2[node] = ecnt * w;
    float4 d0 = add[(size_t)node * 16 + 2 * c];
    float4 d1 = add[(size_t)node * 16 + 2 * c + 1];
    float f[8];
    f[0] = d0.x + acc[0] * w;
    f[1] = d0.y + acc[1] * w;
    f[2] = d0.z + acc[2] * w;
    f[3] = d0.w + acc[3] * w;
    f[4] = d1.x + acc[4] * w;
    f[5] = d1.y + acc[5] * w;
    f[6] = d1.z + acc[6] * w;
    f[7] = d1.w + acc[7] * w;
    if (mode == 2) {
        float a = g_e1[node], b = g_e2[node];
        #pragma unroll
        for (int i = 0; i < 8; ++i) {
            int col = c * 8 + i;
            f[i] += g_r[col] + a * g_r[64 + col] + b * g_r[128 + col];
        }
        float4* o = (float4*)out;
        o[(size_t)node * 16 + 2 * c]     = make_float4(f[0], f[1], f[2], f[3]);
        o[(size_t)node * 16 + 2 * c + 1] = make_float4(f[4], f[5], f[6], f[7]);
    } else {
        uint4 hv;
        __half2 h0 = __floats2half2_rn(f[0], f[1]);
        __half2 h1 = __floats2half2_rn(f[2], f[3]);
        __half2 h2 = __floats2half2_rn(f[4], f[5]);
        __half2 h3 = __floats2half2_rn(f[6], f[7]);
        hv.x = *(uint32_t*)&h0; hv.y = *(uint32_t*)&h1;
        hv.z = *(uint32_t*)&h2; hv.w = *(uint32_t*)&h3;
        ((uint4*)out)[(size_t)node * 8 + c] = hv;
    }
}

// ---------------- mma.sync bf16 split GEMM, 512 threads, fused mainloop ------
#define LDK 136
#define SM_AH 0
#define SM_AL (128 * LDK)
#define SM_BH (2 * 128 * LDK)
#define SM_BL (3 * 128 * LDK)
#define SM_HALVES (4 * 128 * LDK)

#define MMA16816(c, a, b0_, b1_) \
    asm volatile("mma.sync.aligned.m16n8k16.row.col.f32.bf16.bf16.f32 " \
        "{%0,%1,%2,%3}, {%4,%5,%6,%7}, {%8,%9}, {%0,%1,%2,%3};" \
        : "+f"((c)[0]), "+f"((c)[1]), "+f"((c)[2]), "+f"((c)[3]) \
        : "r"((a)[0]), "r"((a)[1]), "r"((a)[2]), "r"((a)[3]), \
          "r"(b0_), "r"(b1_))

#define LDSM4(r0, r1, r2, r3, addr) \
    asm volatile("ldmatrix.sync.aligned.m8n8.x4.shared.b16 {%0,%1,%2,%3}, [%4];" \
        : "=r"(r0), "=r"(r1), "=r"(r2), "=r"(r3) : "r"(addr))

#define CPASYNC16(dst, src) \
    asm volatile("cp.async.ca.shared.global [%0], [%1], 16;" \
        :: "r"(dst), "l"(src) : "memory")

__global__ __launch_bounds__(512, 1)
void k_wgemm(const float* __restrict__ x, const __nv_bfloat16* __restrict__ CTh,
             const __nv_bfloat16* __restrict__ CTl, float* __restrict__ U,
             __half* __restrict__ u3h, int M) {
    extern __shared__ __nv_bfloat16 sm[];
    __nv_bfloat16* Ah = sm + SM_AH;
    __nv_bfloat16* Al = sm + SM_AL;
    __nv_bfloat16* Bh = sm + SM_BH;
    __nv_bfloat16* Bl = sm + SM_BL;

    const int tid = threadIdx.x;
    const int bm = blockIdx.y * 128;
    const int colbase = blockIdx.x * 128;
    const __nv_bfloat16* cth = CTh + (size_t)colbase * 128;
    const __nv_bfloat16* ctl = CTl + (size_t)colbase * 128;

    const int r = tid >> 2;         // 0..127
    const int q = tid & 3;          // 32-col quarter

    // ---- stage B via cp.async (4 x 16B per thread per h/l) ----
    {
        const char* shp = (const char*)(cth + (size_t)r * 128 + q * 32);
        const char* slp = (const char*)(ctl + (size_t)r * 128 + q * 32);
        uint32_t dh = (uint32_t)__cvta_generic_to_shared(Bh + r * LDK + q * 32);
        uint32_t dl = (uint32_t)__cvta_generic_to_shared(Bl + r * LDK + q * 32);
        #pragma unroll
        for (int j = 0; j < 4; ++j) {
            CPASYNC16(dh + 16 * j, shp + 16 * j);
            CPASYNC16(dl + 16 * j, slp + 16 * j);
        }
        asm volatile("cp.async.commit_group;" ::: "memory");
    }

    // ---- stage A: 8 batched float4 loads + convert (32 cols per thread) ----
    {
        int grow = bm + r;
        const float4* xr = (const float4*)(x + (size_t)grow * 128 + q * 32);
        __nv_bfloat16* ah = Ah + r * LDK + q * 32;
        __nv_bfloat16* al = Al + r * LDK + q * 32;
        float4 v[8];
        if (grow < M) {
            #pragma unroll
            for (int j = 0; j < 8; ++j) v[j] = xr[j];
        } else {
            #pragma unroll
            for (int j = 0; j < 8; ++j) v[j] = make_float4(0.f, 0.f, 0.f, 0.f);
        }
        #pragma unroll
        for (int j = 0; j < 4; ++j) {
            float f[8];
            float4 v0 = v[2 * j], v1 = v[2 * j + 1];
            f[0] = v0.x; f[1] = v0.y; f[2] = v0.z; f[3] = v0.w;
            f[4] = v1.x; f[5] = v1.y; f[6] = v1.z; f[7] = v1.w;
            uint32_t hp[4], lp[4];
            #pragma unroll
            for (int e = 0; e < 4; ++e) {
                __nv_bfloat16 h0 = __float2bfloat16(f[2 * e]);
                __nv_bfloat16 h1 = __float2bfloat16(f[2 * e + 1]);
                float l0 = f[2 * e]     - __bfloat162float(h0);
                float l1 = f[2 * e + 1] - __bfloat162float(h1);
                __nv_bfloat162 hh = __halves2bfloat162(h0, h1);
                __nv_bfloat162 lv = __halves2bfloat162(__float2bfloat16(l0),
                                                       __float2bfloat16(l1));
                hp[e] = *(uint32_t*)&hh;
                lp[e] = *(uint32_t*)&lv;
            }
            *(uint4*)(ah + 8 * j) = make_uint4(hp[0], hp[1], hp[2], hp[3]);
            *(uint4*)(al + 8 * j) = make_uint4(lp[0], lp[1], lp[2], lp[3]);
        }
    }
    asm volatile("cp.async.wait_group 0;" ::: "memory");
    __syncthreads();

    const int w = tid >> 5, lane = tid & 31;
    const int wm = (w >> 2) * 32;          // 4 m-groups of 32 rows
    const int wn = (w & 3) * 32;           // 4 n-groups of 32 cols
    const int lr = lane >> 2;
    const int lc = (lane & 3) * 2;
    const int g  = lane >> 3, gl = lane & 7;
    const int a_r = (g & 1) * 8 + gl;
    const int a_c = (g >> 1) * 8;
    const int b_r = (g >> 1) * 8 + gl;
    const int b_c = (g & 1) * 8;

    float acc[2][4][4];
    #pragma unroll
    for (int i = 0; i < 2; ++i)
        #pragma unroll
        for (int j = 0; j < 4; ++j)
            #pragma unroll
            for (int e = 0; e < 4; ++e) acc[i][j][e] = 0.f;

    // single-pass mainloop: load each fragment once, issue all 3 products
    #pragma unroll
    for (int ks = 0; ks < 8; ++ks) {
        int kb = ks * 16;
        uint32_t ah[2][4], al[2][4];
        #pragma unroll
        for (int fm = 0; fm < 2; ++fm) {
            uint32_t addr_h = (uint32_t)__cvta_generic_to_shared(
                &Ah[(wm + fm * 16 + a_r) * LDK + kb + a_c]);
            LDSM4(ah[fm][0], ah[fm][1], ah[fm][2], ah[fm][3], addr_h);
            uint32_t addr_l = (uint32_t)__cvta_generic_to_shared(
                &Al[(wm + fm * 16 + a_r) * LDK + kb + a_c]);
            LDSM4(al[fm][0], al[fm][1], al[fm][2], al[fm][3], addr_l);
        }
        uint32_t bh[4][2], bl[4][2];
        #pragma unroll
        for (int p = 0; p < 2; ++p) {
            uint32_t addr_h = (uint32_t)__cvta_generic_to_shared(
                &Bh[(wn + p * 16 + b_r) * LDK + kb + b_c]);
            LDSM4(bh[2 * p][0], bh[2 * p][1], bh[2 * p + 1][0], bh[2 * p + 1][1], addr_h);
            uint32_t addr_l = (uint32_t)__cvta_generic_to_shared(
                &Bl[(wn + p * 16 + b_r) * LDK + kb + b_c]);
            LDSM4(bl[2 * p][0], bl[2 * p][1], bl[2 * p + 1][0], bl[2 * p + 1][1], addr_l);
        }
        #pragma unroll
        for (int fn = 0; fn < 4; ++fn)
            #pragma unroll
            for (int fm = 0; fm < 2; ++fm) {
                MMA16816(acc[fm][fn], ah[fm], bh[fn][0], bh[fn][1]);
                MMA16816(acc[fm][fn], ah[fm], bl[fn][0], bl[fn][1]);
                MMA16816(acc[fm][fn], al[fm], bh[fn][0], bh[fn][1]);
            }
    }

    #pragma unroll
    for (int fm = 0; fm < 2; ++fm) {
        int r0 = bm + wm + fm * 16 + lr;
        int r1 = r0 + 8;
        #pragma unroll
        for (int fn = 0; fn < 4; ++fn) {
            int col = colbase + wn + fn * 8 + lc;
            int chunk = col >> 6, off = col & 63;
            if (chunk == 3) {
                if (r0 < M) {
                    __half2 h = __floats2half2_rn(acc[fm][fn][0], acc[fm][fn][1]);
                    *(__half2*)(u3h + (size_t)r0 * 64 + off) = h;
                }
                if (r1 < M) {
                    __half2 h = __floats2half2_rn(acc[fm][fn][2], acc[fm][fn][3]);
                    *(__half2*)(u3h + (size_t)r1 * 64 + off) = h;
                }
            } else {
                float* dst = U + (size_t)chunk * NN * 64 + off;
                if (r0 < M)
                    *(float2*)(dst + (size_t)r0 * 64) =
                        make_float2(acc[fm][fn][0], acc[fm][fn][1]);
                if (r1 < M)
                    *(float2*)(dst + (size_t)r1 * 64) =
                        make_float2(acc[fm][fn][2], acc[fm][fn][3]);
            }
        }
    }
}

// ---------------- launch ----------------
extern "C" void kernel_launch(void* const* d_in, const int* in_sizes, int n_in,
                              void* d_out, int out_size) {
    const float* x    = (const float*)d_in[0];
    const int*   esrc = (const int*)d_in[1];
    const int*   edst = (const int*)d_in[2];
    const float* W0s  = (const float*)d_in[3];
    const float* W0n  = (const float*)d_in[4];
    const float* b0   = (const float*)d_in[5];
    const float* W1s  = (const float*)d_in[6];
    const float* W1n  = (const float*)d_in[7];
    const float* b1   = (const float*)d_in[8];
    const float* W2s  = (const float*)d_in[9];
    const float* W2n  = (const float*)d_in[10];
    const float* b2   = (const float*)d_in[11];
    const float* Wfc  = (const float*)d_in[12];
    const float* bfc  = (const float*)d_in[13];
    float* out = (float*)d_out;

    float *U;
    __half *sh;
    __nv_bfloat16 *CTh, *CTl;
    cudaGetSymbolAddress((void**)&U,   g_U);
    cudaGetSymbolAddress((void**)&sh,  g_sh);
    cudaGetSymbolAddress((void**)&CTh, g_CTh);
    cudaGetSymbolAddress((void**)&CTl, g_CTl);

    const int TB = 256;
    int nblk_n = (NN + TB - 1) / TB;
    int nblk_e = (NE + TB - 1) / TB;
    int ntiles = (NN + 1023) / 1024;

    size_t smem_bytes = (size_t)SM_HALVES * sizeof(__nv_bfloat16);
    cudaFuncSetAttribute(k_wgemm, cudaFuncAttributeMaxDynamicSharedMemorySize,
                         (int)smem_bytes);

    cudaStream_t s2;
    cudaStreamCreateWithFlags(&s2, cudaStreamNonBlocking);
    cudaEvent_t eFork, ePre, eJoin;
    cudaEventCreateWithFlags(&eFork, cudaEventDisableTiming);
    cudaEventCreateWithFlags(&ePre,  cudaEventDisableTiming);
    cudaEventCreateWithFlags(&eJoin, cudaEventDisableTiming);

    cudaEventRecord(eFork, 0);
    cudaStreamWaitEvent(s2, eFork, 0);

    __half* u3h = (__half*)(U + (size_t)3 * NN * 64);

    // ---- chain B (s2): precompute -> full GEMM ----
    k_preA<<<(2 * 16384 + TB - 1) / TB, TB, 0, s2>>>(W2s, W2n, Wfc);
    k_preB<<<(3 * 16384 + TB - 1) / TB, TB, 0, s2>>>(W1s, W1n);
    k_preC<<<(4 * 8192 + TB - 1) / TB, TB, 0, s2>>>(W0s, W0n);
    cudaEventRecord(ePre, s2);
    {
        dim3 gG(2, (NN + 127) / 128);
        k_wgemm<<<gG, 512, smem_bytes, s2>>>(x, CTh, CTl, U, u3h, NN);
    }
    cudaEventRecord(eJoin, s2);

    // ---- chain A (default stream): CSR build, then rvec ----
    k_zero_counts<<<nblk_n, TB>>>();
    k_count<<<nblk_e, TB>>>(edst);
    k_scan_tiles<<<ntiles, 1024>>>();
    k_scan_sums<<<1, 64>>>(ntiles);
    k_scan_fix<<<nblk_n, TB>>>();
    k_fill<<<nblk_e, TB>>>(esrc, edst);
    cudaStreamWaitEvent(0, ePre, 0);
    k_rvec<<<24, 256>>>(b0, b1, b2, bfc, Wfc);

    // join
    cudaStreamWaitEvent(0, eJoin, 0);

    // ---- Horner aggregation (fp16 srcs, fp16-native accumulation) ----
    const float4* u0 = (const float4*)U;
    const float4* u1 = (const float4*)(U + (size_t)1 * NN * 64);
    const float4* u2 = (const float4*)(U + (size_t)2 * NN * 64);
    __half* s2h = sh;
    __half* s1h = sh + (size_t)NN * 64;
    int gblk = (NN * 8 + TB - 1) / TB;
    k_gather64h<<<gblk, TB>>>((const uint4*)u3h, u2, s2h, 1);
    k_gather64h<<<gblk, TB>>>((const uint4*)s2h, u1, s1h, 0);
    k_gather64h<<<gblk, TB>>>((const uint4*)s1h, u0, out, 2);
}